// round 11
// baseline (speedup 1.0000x reference)
#include <cuda_runtime.h>
#include <cuda_bf16.h>
#include <math.h>
#include <stdint.h>

// ---------------- problem constants ----------------
#define BATCH   4
#define SEQ     4096
#define DMODEL  1024
#define DSTATE  16
#define DCONV   4
#define NHEADS  8
#define CHUNKL  64
#define DINNER  2048
#define HEADDIM 256
#define CONVDIM 2080              // DINNER + 2*DSTATE
#define DPROJ   4136              // 2*DINNER + 2*DSTATE + NHEADS
#define NROWS   (BATCH*SEQ)       // 16384
#define NCHUNK  (SEQ/CHUNKL)      // 64
#define NPAD1   4352              // 17*256 padded N for GEMM1

// ---------------- scratch (static device globals) ----------------
__device__ float g_z     [NROWS*(size_t)DINNER];
__device__ float g_xBC   [NROWS*(size_t)CONVDIM];
__device__ float g_dt    [NROWS*(size_t)NHEADS];
__device__ float g_xh    [NROWS*(size_t)DINNER];
__device__ float g_Bm    [NROWS*(size_t)DSTATE];
__device__ float g_Cm    [NROWS*(size_t)DSTATE];
__device__ float g_states[(size_t)BATCH*NCHUNK*NHEADS*HEADDIM*DSTATE];
__device__ float g_Pst   [(size_t)BATCH*NCHUNK*NHEADS*HEADDIM*DSTATE];
__device__ float g_Y     [NROWS*(size_t)DINNER];

// bf16 hi/lo split buffers
__device__ __nv_bfloat16 g_Xhi [NROWS*(size_t)DMODEL];
__device__ __nv_bfloat16 g_Xlo [NROWS*(size_t)DMODEL];
__device__ __nv_bfloat16 g_W1hi[(size_t)NPAD1*DMODEL];
__device__ __nv_bfloat16 g_W1lo[(size_t)NPAD1*DMODEL];
__device__ __nv_bfloat16 g_W2hi[(size_t)DMODEL*DINNER];
__device__ __nv_bfloat16 g_W2lo[(size_t)DMODEL*DINNER];
__device__ __nv_bfloat16 g_Yhi [NROWS*(size_t)DINNER];
__device__ __nv_bfloat16 g_Ylo [NROWS*(size_t)DINNER];

__device__ __forceinline__ float softplus_f(float x) {
    return (x > 20.f) ? x : log1pf(expf(x));
}
__device__ __forceinline__ float silu_f(float x) {
    return x / (1.f + expf(-x));
}

__device__ __forceinline__ uint32_t smem_u32(const void* p) {
    uint32_t a;
    asm("{ .reg .u64 t; cvta.to.shared.u64 t, %1; cvt.u32.u64 %0, t; }"
        : "=r"(a) : "l"(p));
    return a;
}

#define CP_COMMIT() asm volatile("cp.async.commit_group;" ::: "memory")
#define CP_WAIT_N(n) asm volatile("cp.async.wait_group %0;" :: "n"(n) : "memory")

__device__ __forceinline__ void ldmat_x4(uint32_t a, uint32_t& r0, uint32_t& r1,
                                         uint32_t& r2, uint32_t& r3) {
    asm volatile("ldmatrix.sync.aligned.m8n8.x4.shared.b16 {%0,%1,%2,%3}, [%4];"
                 : "=r"(r0), "=r"(r1), "=r"(r2), "=r"(r3) : "r"(a));
}
__device__ __forceinline__ void mma_bf16(float* c, uint32_t a0, uint32_t a1,
                                         uint32_t a2, uint32_t a3,
                                         uint32_t b0, uint32_t b1) {
    asm volatile(
        "mma.sync.aligned.m16n8k16.row.col.f32.bf16.bf16.f32 "
        "{%0,%1,%2,%3}, {%4,%5,%6,%7}, {%8,%9}, {%0,%1,%2,%3};"
        : "+f"(c[0]), "+f"(c[1]), "+f"(c[2]), "+f"(c[3])
        : "r"(a0), "r"(a1), "r"(a2), "r"(a3), "r"(b0), "r"(b1));
}

// copy an ROWSxk64-bf16 tile (128B rows, SW128 swizzle) global->smem via cp.async
// 256 threads; NCH16 = rows*8 total 16B chunks
template<int NCH16>
__device__ __forceinline__ void load_tile(uint32_t sbase, const __nv_bfloat16* g,
                                          int rowbase, int K, int k0, int tid) {
    #pragma unroll
    for (int it = 0; it < NCH16 / 256; it++) {
        int chunk = tid + it * 256;
        int row = chunk >> 3;
        int c16 = chunk & 7;
        uint32_t soff = (uint32_t)(row * 128 + c16 * 16);
        soff ^= ((soff >> 3) & 0x70);        // SW128
        const void* gp = g + (size_t)(rowbase + row) * K + k0 + c16 * 8;
        asm volatile("cp.async.cg.shared.global [%0], [%1], 16;"
                     :: "r"(sbase + soff), "l"(gp) : "memory");
    }
}

// swizzled shared address within a (rows)x64-bf16 tile
__device__ __forceinline__ uint32_t tile_addr(uint32_t base, int row, int colb) {
    uint32_t off = (uint32_t)(row * 128 + colb);
    off ^= ((off >> 3) & 0x70);
    return base + off;
}

// ============================================================================
// mma.sync bf16 GEMM (NT): C[M,Npad] = A[M,K] * B[Npad,K]^T, hi/lo split, f32 acc
// CTA tile 128x256, K-chunk 64, 2-stage cp.async double buffer, 256 threads
// (8 warps 2x4, warp tile 64x64 -> LDS:MMA = 1:3).
// MODE 0: in-proj epilogue; MODE 1: plain f32 store.
// ============================================================================
#define STAGE_BYTES 98304        // Ahi 16K + Alo 16K + Bhi 32K + Blo 32K

template<int MODE>
__global__ __launch_bounds__(256, 1)
void mma_gemm(const __nv_bfloat16* __restrict__ Ahi, const __nv_bfloat16* __restrict__ Alo,
              const __nv_bfloat16* __restrict__ Bhi, const __nv_bfloat16* __restrict__ Blo,
              int K, float* __restrict__ out, const float* __restrict__ dt_bias)
{
    extern __shared__ char smem[];
    const uint32_t sb = smem_u32(smem);
    const int tid = threadIdx.x;
    const int wid = tid >> 5;
    const int lane = tid & 31;
    const int row0 = blockIdx.y * 128;
    const int col0 = blockIdx.x * 256;
    const int NC = K / 64;

    const int wm = wid >> 2;          // 0..1 : warp row (64 rows)
    const int wn = wid & 3;           // 0..3 : warp col (64 cols)

    float acc[4][8][4];               // [mt][nj][reg] = 128 regs
    #pragma unroll
    for (int i = 0; i < 4; i++)
        #pragma unroll
        for (int j = 0; j < 8; j++)
            #pragma unroll
            for (int r = 0; r < 4; r++) acc[i][j][r] = 0.f;

    // ldmatrix lane addressing
    const int grp = lane >> 3;        // 0..3
    const int wit = lane & 7;         // 0..7
    const int a_r = wit + (grp & 1) * 8;
    const int a_c = (grp >> 1) * 16;
    const int b_r = wit + (grp >> 1) * 8;
    const int b_c = (grp & 1) * 16;

    // prologue: chunk 0 -> stage 0
    load_tile<1024>(sb,         Ahi, row0, K, 0, tid);
    load_tile<1024>(sb + 16384, Alo, row0, K, 0, tid);
    load_tile<2048>(sb + 32768, Bhi, col0, K, 0, tid);
    load_tile<2048>(sb + 65536, Blo, col0, K, 0, tid);
    CP_COMMIT();

    for (int i = 0; i < NC; i++) {
        if (i + 1 < NC) {
            uint32_t stb = sb + ((i + 1) & 1) * STAGE_BYTES;
            load_tile<1024>(stb,         Ahi, row0, K, (i + 1) * 64, tid);
            load_tile<1024>(stb + 16384, Alo, row0, K, (i + 1) * 64, tid);
            load_tile<2048>(stb + 32768, Bhi, col0, K, (i + 1) * 64, tid);
            load_tile<2048>(stb + 65536, Blo, col0, K, (i + 1) * 64, tid);
            CP_COMMIT();
            CP_WAIT_N(1);
        } else {
            CP_WAIT_N(0);
        }
        __syncthreads();

        const uint32_t sAh = sb + (i & 1) * STAGE_BYTES;
        const uint32_t sAl = sAh + 16384;
        const uint32_t sBh = sAh + 32768;
        const uint32_t sBl = sAh + 65536;

        #pragma unroll
        for (int ks = 0; ks < 4; ks++) {
            const int kb = ks * 32;   // byte offset of this k16 within 128B row

            uint32_t ah[4][4], al[4][4];
            #pragma unroll
            for (int mt = 0; mt < 4; mt++) {
                int r = wm * 64 + mt * 16 + a_r;
                ldmat_x4(tile_addr(sAh, r, kb + a_c),
                         ah[mt][0], ah[mt][1], ah[mt][2], ah[mt][3]);
                ldmat_x4(tile_addr(sAl, r, kb + a_c),
                         al[mt][0], al[mt][1], al[mt][2], al[mt][3]);
            }
            uint32_t bh[8][2], bl[8][2];
            #pragma unroll
            for (int np = 0; np < 4; np++) {   // covers n8 tiles 2np, 2np+1
                int r = wn * 64 + np * 16 + b_r;
                uint32_t t0, t1, t2, t3;
                ldmat_x4(tile_addr(sBh, r, kb + b_c), t0, t1, t2, t3);
                bh[2*np][0] = t0; bh[2*np][1] = t1;
                bh[2*np+1][0] = t2; bh[2*np+1][1] = t3;
                ldmat_x4(tile_addr(sBl, r, kb + b_c), t0, t1, t2, t3);
                bl[2*np][0] = t0; bl[2*np][1] = t1;
                bl[2*np+1][0] = t2; bl[2*np+1][1] = t3;
            }

            #pragma unroll
            for (int mt = 0; mt < 4; mt++)
                #pragma unroll
                for (int nj = 0; nj < 8; nj++) {
                    mma_bf16(acc[mt][nj], ah[mt][0], ah[mt][1], ah[mt][2], ah[mt][3],
                             bh[nj][0], bh[nj][1]);
                    mma_bf16(acc[mt][nj], ah[mt][0], ah[mt][1], ah[mt][2], ah[mt][3],
                             bl[nj][0], bl[nj][1]);
                    mma_bf16(acc[mt][nj], al[mt][0], al[mt][1], al[mt][2], al[mt][3],
                             bh[nj][0], bh[nj][1]);
                }
        }
        __syncthreads();
    }

    // epilogue: direct global stores (each 4-lane quad covers a 32B sector)
    #pragma unroll
    for (int mt = 0; mt < 4; mt++) {
        #pragma unroll
        for (int nj = 0; nj < 8; nj++) {
            int m = row0 + wm * 64 + mt * 16 + (lane >> 2);
            int n = col0 + wn * 64 + nj * 8 + (lane & 3) * 2;
            #pragma unroll
            for (int half = 0; half < 2; half++) {
                int mm = m + half * 8;
                float v0 = acc[mt][nj][half * 2 + 0];
                float v1 = acc[mt][nj][half * 2 + 1];
                if (MODE == 1) {
                    out[(size_t)mm * DMODEL + n]     = v0;
                    out[(size_t)mm * DMODEL + n + 1] = v1;
                } else {
                    #pragma unroll
                    for (int e = 0; e < 2; e++) {
                        int nn = n + e;
                        float v = e ? v1 : v0;
                        if (nn < DINNER) {
                            g_z[(size_t)mm * DINNER + nn] = v;
                        } else if (nn < DINNER + CONVDIM) {
                            g_xBC[(size_t)mm * CONVDIM + (nn - DINNER)] = v;
                        } else if (nn < DPROJ) {
                            int h = nn - (DINNER + CONVDIM);
                            g_dt[(size_t)mm * NHEADS + h] =
                                softplus_f(v + dt_bias[h]);
                        }
                    }
                }
            }
        }
    }
}

// ============================================================================
// hi/lo split kernels
// ============================================================================
__global__ void split_plain(const float* __restrict__ src,
                            __nv_bfloat16* __restrict__ hi,
                            __nv_bfloat16* __restrict__ lo, int n)
{
    int i = blockIdx.x * blockDim.x + threadIdx.x;
    if (i >= n) return;
    float x = src[i];
    __nv_bfloat16 h = __float2bfloat16(x);
    hi[i] = h;
    lo[i] = __float2bfloat16(x - __bfloat162float(h));
}

__global__ void split_w1_pad(const float* __restrict__ W)
{
    int i = blockIdx.x * blockDim.x + threadIdx.x;   // over NPAD1*DMODEL
    if (i >= NPAD1 * DMODEL) return;
    int r = i / DMODEL;
    float x = (r < DPROJ) ? W[(size_t)r * DMODEL + (i - r * DMODEL)] : 0.f;
    __nv_bfloat16 h = __float2bfloat16(x);
    g_W1hi[i] = h;
    g_W1lo[i] = __float2bfloat16(x - __bfloat162float(h));
}

// ============================================================================
// Causal depthwise conv + SiLU + split
// ============================================================================
__global__ void conv_silu_kernel(const float* __restrict__ conv_w,
                                 const float* __restrict__ conv_b)
{
    const int row = blockIdx.x;
    const int b = row / SEQ;
    const int l = row - b * SEQ;
    for (int ch = threadIdx.x; ch < CONVDIM; ch += blockDim.x) {
        float acc = conv_b[ch];
        #pragma unroll
        for (int j = 0; j < DCONV; j++) {
            int ls = l - (DCONV - 1) + j;
            if (ls >= 0)
                acc += conv_w[ch * DCONV + j] *
                       g_xBC[(size_t)(b * SEQ + ls) * CONVDIM + ch];
        }
        float v = silu_f(acc);
        if (ch < DINNER) {
            int h = ch >> 8;
            g_xh[(size_t)row * DINNER + ch] = v * g_dt[(size_t)row * NHEADS + h];
        } else if (ch < DINNER + DSTATE) {
            g_Bm[(size_t)row * DSTATE + (ch - DINNER)] = v;
        } else {
            g_Cm[(size_t)row * DSTATE + (ch - DINNER - DSTATE)] = v;
        }
    }
}

// ============================================================================
// Per-chunk states
// ============================================================================
__global__ void chunk_states_kernel(const float* __restrict__ log_A)
{
    const int id = blockIdx.x;
    const int b = id >> 9;
    const int rem = id & 511;
    const int c = rem >> 3;
    const int h = rem & 7;
    const float a = -expf(log_A[h]);

    __shared__ float Bs[CHUNKL][DSTATE];
    const int t = threadIdx.x;
    for (int i = t; i < CHUNKL * DSTATE; i += 256)
        Bs[i >> 4][i & 15] =
            g_Bm[(size_t)(b * SEQ + c * CHUNKL + (i >> 4)) * DSTATE + (i & 15)];
    __syncthreads();

    float acc[DSTATE];
    #pragma unroll
    for (int n = 0; n < DSTATE; n++) acc[n] = 0.f;

    const int p = t;
    for (int s = 0; s < CHUNKL; s++) {
        float xv = g_xh[(size_t)(b * SEQ + c * CHUNKL + s) * DINNER + h * HEADDIM + p];
        float w = expf(a * (float)(CHUNKL - 1 - s)) * xv;
        #pragma unroll
        for (int n = 0; n < DSTATE; n++) acc[n] += Bs[s][n] * w;
    }
    size_t base = ((size_t)id * HEADDIM + p) * DSTATE;
    #pragma unroll
    for (int n = 0; n < DSTATE; n++) g_states[base + n] = acc[n];
}

// ============================================================================
// Inter-chunk scan
// ============================================================================
__global__ void state_scan_kernel(const float* __restrict__ log_A)
{
    const int gid = blockIdx.x * blockDim.x + threadIdx.x;
    const int b = gid >> 15;
    const int r = gid & 32767;
    const int h = r >> 12;
    const float a = -expf(log_A[h]);
    const float d = expf(a * (float)CHUNKL);
    float P = 0.f;
    for (int c = 0; c < NCHUNK; c++) {
        size_t off = (size_t)(b * NCHUNK + c) * 32768 + r;
        g_Pst[off] = P;
        P = d * P + g_states[off];
    }
}

// ============================================================================
// SSD Y kernel
// ============================================================================
__global__ void ssd_y_kernel(const float* __restrict__ log_A,
                             const float* __restrict__ D_skip)
{
    extern __shared__ float sh[];
    float* Bs = sh;
    float* Cs = sh + 1024;
    float* G  = sh + 2048;
    float* xs = sh + 2048 + 4096;

    const int id = blockIdx.x;
    const int b = id >> 9;
    const int rem = id & 511;
    const int c = rem >> 3;
    const int h = rem & 7;
    const float a = -expf(log_A[h]);
    const int t = threadIdx.x;
    const int rowbase = b * SEQ + c * CHUNKL;

    for (int i = t; i < CHUNKL * DSTATE; i += 256) {
        size_t gi = (size_t)(rowbase + (i >> 4)) * DSTATE + (i & 15);
        Bs[i] = g_Bm[gi];
        Cs[i] = g_Cm[gi];
    }
    for (int i = t; i < CHUNKL * HEADDIM; i += 256) {
        int s = i >> 8, p = i & 255;
        xs[i] = g_xh[(size_t)(rowbase + s) * DINNER + h * HEADDIM + p];
    }
    __syncthreads();

    for (int e = t * 16; e < t * 16 + 16; e++) {
        int tt = e >> 6, ss = e & 63;
        float val = 0.f;
        if (ss <= tt) {
            float dot = 0.f;
            #pragma unroll
            for (int n = 0; n < DSTATE; n++) dot += Cs[tt * 16 + n] * Bs[ss * 16 + n];
            val = expf(a * (float)(tt - ss)) * dot;
        }
        G[e] = val;
    }
    __syncthreads();

    const int p = t;
    float Preg[DSTATE];
    size_t pbase = ((size_t)id * HEADDIM + p) * DSTATE;
    #pragma unroll
    for (int n = 0; n < DSTATE; n++) Preg[n] = g_Pst[pbase + n];
    const float dsk = D_skip[h];

    for (int tt = 0; tt < CHUNKL; tt++) {
        float acc = 0.f;
        const float* Gr = &G[tt * 64];
        for (int ss = 0; ss <= tt; ss++) acc += Gr[ss] * xs[ss * 256 + p];
        float offv = 0.f;
        #pragma unroll
        for (int n = 0; n < DSTATE; n++) offv += Cs[tt * 16 + n] * Preg[n];
        float y = acc + expf(a * (float)(tt + 1)) * offv + dsk * xs[tt * 256 + p];
        g_Y[(size_t)(rowbase + tt) * DINNER + h * HEADDIM + p] = y;
    }
}

// ============================================================================
// Gate + RMS norm; emits bf16 hi/lo for GEMM2
// ============================================================================
__global__ void rms_gate_kernel(const float* __restrict__ norm_w)
{
    const int row = blockIdx.x;
    const int t = threadIdx.x;
    float v[8];
    float ss = 0.f;
    #pragma unroll
    for (int k = 0; k < 8; k++) {
        int ch = k * 256 + t;
        float Yv = g_Y[(size_t)row * DINNER + ch];
        float zv = g_z[(size_t)row * DINNER + ch];
        float val = Yv * silu_f(zv);
        v[k] = val;
        ss += val * val;
    }
    __shared__ float red[256];
    red[t] = ss;
    __syncthreads();
    for (int st = 128; st > 0; st >>= 1) {
        if (t < st) red[t] += red[t + st];
        __syncthreads();
    }
    float inv = rsqrtf(red[0] / (float)DINNER + 1e-5f);
    #pragma unroll
    for (int k = 0; k < 8; k++) {
        int ch = k * 256 + t;
        float val = v[k] * inv * norm_w[ch];
        __nv_bfloat16 hv = __float2bfloat16(val);
        g_Yhi[(size_t)row * DINNER + ch] = hv;
        g_Ylo[(size_t)row * DINNER + ch] =
            __float2bfloat16(val - __bfloat162float(hv));
    }
}

// ============================================================================
// Launch
// ============================================================================
extern "C" void kernel_launch(void* const* d_in, const int* in_sizes, int n_in,
                              void* d_out, int out_size)
{
    const float* input   = (const float*)d_in[0];
    const float* W_in    = (const float*)d_in[1];
    const float* conv_w  = (const float*)d_in[2];
    const float* conv_b  = (const float*)d_in[3];
    const float* dt_bias = (const float*)d_in[4];
    const float* log_A   = (const float*)d_in[5];
    const float* D_skip  = (const float*)d_in[6];
    const float* norm_w  = (const float*)d_in[7];
    const float* W_out   = (const float*)d_in[8];
    float* out = (float*)d_out;

    (void)in_sizes; (void)n_in; (void)out_size;

    const int GSMEM = 2 * STAGE_BYTES;               // 196608 B
    const int SMEM_Y = (1024 + 1024 + 4096 + 16384) * 4;
    cudaFuncSetAttribute(mma_gemm<0>, cudaFuncAttributeMaxDynamicSharedMemorySize, GSMEM);
    cudaFuncSetAttribute(mma_gemm<1>, cudaFuncAttributeMaxDynamicSharedMemorySize, GSMEM);
    cudaFuncSetAttribute(ssd_y_kernel, cudaFuncAttributeMaxDynamicSharedMemorySize, SMEM_Y);

    __nv_bfloat16 *Xhi, *Xlo, *W2hi, *W2lo, *Yhi, *Ylo, *W1hi, *W1lo;
    cudaGetSymbolAddress((void**)&Xhi,  g_Xhi);
    cudaGetSymbolAddress((void**)&Xlo,  g_Xlo);
    cudaGetSymbolAddress((void**)&W2hi, g_W2hi);
    cudaGetSymbolAddress((void**)&W2lo, g_W2lo);
    cudaGetSymbolAddress((void**)&Yhi,  g_Yhi);
    cudaGetSymbolAddress((void**)&Ylo,  g_Ylo);
    cudaGetSymbolAddress((void**)&W1hi, g_W1hi);
    cudaGetSymbolAddress((void**)&W1lo, g_W1lo);

    // splits
    {
        int n = NROWS * DMODEL;
        split_plain<<<(n + 255) / 256, 256>>>(input, Xhi, Xlo, n);
    }
    split_w1_pad<<<(NPAD1 * DMODEL + 255) / 256, 256>>>(W_in);
    {
        int n = DMODEL * DINNER;
        split_plain<<<(n + 255) / 256, 256>>>(W_out, W2hi, W2lo, n);
    }

    // 1) in-projection (mma.sync bf16 split)
    mma_gemm<0><<<dim3(NPAD1 / 256, NROWS / 128), 256, GSMEM>>>(
        Xhi, Xlo, W1hi, W1lo, DMODEL, nullptr, dt_bias);

    // 2) conv + silu + split
    conv_silu_kernel<<<NROWS, 256>>>(conv_w, conv_b);

    // 3) per-chunk states
    chunk_states_kernel<<<BATCH * NCHUNK * NHEADS, 256>>>(log_A);

    // 4) inter-chunk scan
    state_scan_kernel<<<(BATCH * NHEADS * HEADDIM * DSTATE) / 256, 256>>>(log_A);

    // 5) Y
    ssd_y_kernel<<<BATCH * NCHUNK * NHEADS, 256, SMEM_Y>>>(log_A, D_skip);

    // 6) gate + RMS norm (emits bf16 hi/lo)
    rms_gate_kernel<<<NROWS, 256>>>(norm_w);

    // 7) out-projection (mma.sync bf16 split)
    mma_gemm<1><<<dim3(DMODEL / 256, NROWS / 128), 256, GSMEM>>>(
        Yhi, Ylo, W2hi, W2lo, DINNER, out, nullptr);
}

// round 12
// speedup vs baseline: 1.2113x; 1.2113x over previous
#include <cuda_runtime.h>
#include <cuda_fp16.h>
#include <math.h>
#include <stdint.h>

// ---------------- problem constants ----------------
#define BATCH   4
#define SEQ     4096
#define DMODEL  1024
#define DSTATE  16
#define DCONV   4
#define NHEADS  8
#define CHUNKL  64
#define DINNER  2048
#define HEADDIM 256
#define CONVDIM 2080              // DINNER + 2*DSTATE
#define DPROJ   4136              // 2*DINNER + 2*DSTATE + NHEADS
#define NROWS   (BATCH*SEQ)       // 16384
#define NCHUNK  (SEQ/CHUNKL)      // 64
#define NPAD1   4352              // 17*256 padded N for GEMM1

// ---------------- scratch (static device globals) ----------------
__device__ float g_z     [NROWS*(size_t)DINNER];
__device__ float g_xBC   [NROWS*(size_t)CONVDIM];
__device__ float g_dt    [NROWS*(size_t)NHEADS];
__device__ float g_xh    [NROWS*(size_t)DINNER];
__device__ float g_Bm    [NROWS*(size_t)DSTATE];
__device__ float g_Cm    [NROWS*(size_t)DSTATE];
__device__ float g_states[(size_t)BATCH*NCHUNK*NHEADS*HEADDIM*DSTATE];
__device__ float g_Pst   [(size_t)BATCH*NCHUNK*NHEADS*HEADDIM*DSTATE];
__device__ float g_Y     [NROWS*(size_t)DINNER];

// fp16 operand buffers (single precision pass)
__device__ __half g_Xh [NROWS*(size_t)DMODEL];
__device__ __half g_W1h[(size_t)NPAD1*DMODEL];
__device__ __half g_W2h[(size_t)DMODEL*DINNER];
__device__ __half g_Yh [NROWS*(size_t)DINNER];

__device__ __forceinline__ float softplus_f(float x) {
    return (x > 20.f) ? x : log1pf(expf(x));
}
__device__ __forceinline__ float silu_f(float x) {
    return x / (1.f + expf(-x));
}

__device__ __forceinline__ uint32_t smem_u32(const void* p) {
    uint32_t a;
    asm("{ .reg .u64 t; cvta.to.shared.u64 t, %1; cvt.u32.u64 %0, t; }"
        : "=r"(a) : "l"(p));
    return a;
}

#define CP_COMMIT() asm volatile("cp.async.commit_group;" ::: "memory")
#define CP_WAIT_N(n) asm volatile("cp.async.wait_group %0;" :: "n"(n) : "memory")

__device__ __forceinline__ void ldmat_x4(uint32_t a, uint32_t& r0, uint32_t& r1,
                                         uint32_t& r2, uint32_t& r3) {
    asm volatile("ldmatrix.sync.aligned.m8n8.x4.shared.b16 {%0,%1,%2,%3}, [%4];"
                 : "=r"(r0), "=r"(r1), "=r"(r2), "=r"(r3) : "r"(a));
}
__device__ __forceinline__ void mma_f16(float* c, uint32_t a0, uint32_t a1,
                                        uint32_t a2, uint32_t a3,
                                        uint32_t b0, uint32_t b1) {
    asm volatile(
        "mma.sync.aligned.m16n8k16.row.col.f32.f16.f16.f32 "
        "{%0,%1,%2,%3}, {%4,%5,%6,%7}, {%8,%9}, {%0,%1,%2,%3};"
        : "+f"(c[0]), "+f"(c[1]), "+f"(c[2]), "+f"(c[3])
        : "r"(a0), "r"(a1), "r"(a2), "r"(a3), "r"(b0), "r"(b1));
}

// copy a ROWSx64-fp16 tile (128B rows, SW128 swizzle) global->smem via cp.async
// 512 threads; NCH16 = rows*8 total 16B chunks
template<int NCH16>
__device__ __forceinline__ void load_tile(uint32_t sbase, const __half* g,
                                          int rowbase, int K, int k0, int tid) {
    #pragma unroll
    for (int it = 0; it < NCH16 / 512; it++) {
        int chunk = tid + it * 512;
        int row = chunk >> 3;
        int c16 = chunk & 7;
        uint32_t soff = (uint32_t)(row * 128 + c16 * 16);
        soff ^= ((soff >> 3) & 0x70);        // SW128
        const void* gp = g + (size_t)(rowbase + row) * K + k0 + c16 * 8;
        asm volatile("cp.async.cg.shared.global [%0], [%1], 16;"
                     :: "r"(sbase + soff), "l"(gp) : "memory");
    }
}

// swizzled shared address within a (rows)x64-fp16 tile
__device__ __forceinline__ uint32_t tile_addr(uint32_t base, int row, int colb) {
    uint32_t off = (uint32_t)(row * 128 + colb);
    off ^= ((off >> 3) & 0x70);
    return base + off;
}

// ============================================================================
// mma.sync fp16 GEMM (NT): C[M,Npad] = A[M,K] * B[Npad,K]^T, f32 acc.
// CTA tile 128x256, K-chunk 64, 4-stage cp.async pipeline, 512 threads
// (16 warps 4x4, warp tile 32x64). MODE 0: in-proj epilogue; MODE 1: f32 store.
// ============================================================================
#define STAGE_BYTES 49152        // A 16KB + B 32KB
#define A_OFF       0
#define B_OFF       16384

template<int MODE>
__global__ __launch_bounds__(512, 1)
void mma_gemm(const __half* __restrict__ A, const __half* __restrict__ B,
              int K, float* __restrict__ out, const float* __restrict__ dt_bias)
{
    extern __shared__ char smem[];
    const uint32_t sb = smem_u32(smem);
    const int tid = threadIdx.x;
    const int wid = tid >> 5;
    const int lane = tid & 31;
    const int row0 = blockIdx.y * 128;
    const int col0 = blockIdx.x * 256;
    const int NC = K / 64;

    const int wm = wid >> 2;          // 0..3 : warp row (32 rows)
    const int wn = wid & 3;           // 0..3 : warp col (64 cols)

    float acc[2][8][4];               // 64 regs
    #pragma unroll
    for (int i = 0; i < 2; i++)
        #pragma unroll
        for (int j = 0; j < 8; j++)
            #pragma unroll
            for (int r = 0; r < 4; r++) acc[i][j][r] = 0.f;

    // ldmatrix lane addressing
    const int grp = lane >> 3;        // 0..3
    const int wit = lane & 7;         // 0..7
    const int a_r = wit + (grp & 1) * 8;
    const int a_c = (grp >> 1) * 16;
    const int b_r = wit + (grp >> 1) * 8;
    const int b_c = (grp & 1) * 16;

    // prologue: stages 0..2
    #pragma unroll
    for (int i = 0; i < 3; i++) {
        uint32_t stb = sb + i * STAGE_BYTES;
        load_tile<1024>(stb + A_OFF, A, row0, K, i * 64, tid);
        load_tile<2048>(stb + B_OFF, B, col0, K, i * 64, tid);
        CP_COMMIT();
    }

    for (int i = 0; i < NC; i++) {
        if (i + 3 < NC) {
            uint32_t stb = sb + ((i + 3) & 3) * STAGE_BYTES;
            load_tile<1024>(stb + A_OFF, A, row0, K, (i + 3) * 64, tid);
            load_tile<2048>(stb + B_OFF, B, col0, K, (i + 3) * 64, tid);
            CP_COMMIT();
            CP_WAIT_N(3);
        } else {
            CP_WAIT_N(0);
        }
        __syncthreads();

        const uint32_t sA = sb + (i & 3) * STAGE_BYTES + A_OFF;
        const uint32_t sB = sb + (i & 3) * STAGE_BYTES + B_OFF;

        #pragma unroll
        for (int ks = 0; ks < 4; ks++) {
            const int kb = ks * 32;   // byte offset of this k16 within 128B row

            uint32_t ah[2][4];
            #pragma unroll
            for (int mt = 0; mt < 2; mt++) {
                int r = wm * 32 + mt * 16 + a_r;
                ldmat_x4(tile_addr(sA, r, kb + a_c),
                         ah[mt][0], ah[mt][1], ah[mt][2], ah[mt][3]);
            }
            uint32_t bh[8][2];
            #pragma unroll
            for (int np = 0; np < 4; np++) {   // covers n8 tiles 2np, 2np+1
                int r = wn * 64 + np * 16 + b_r;
                uint32_t t0, t1, t2, t3;
                ldmat_x4(tile_addr(sB, r, kb + b_c), t0, t1, t2, t3);
                bh[2*np][0] = t0; bh[2*np][1] = t1;
                bh[2*np+1][0] = t2; bh[2*np+1][1] = t3;
            }

            #pragma unroll
            for (int mt = 0; mt < 2; mt++)
                #pragma unroll
                for (int nj = 0; nj < 8; nj++)
                    mma_f16(acc[mt][nj], ah[mt][0], ah[mt][1], ah[mt][2], ah[mt][3],
                            bh[nj][0], bh[nj][1]);
        }
        __syncthreads();
    }

    // epilogue: direct global stores (each 4-lane quad covers a 32B sector)
    #pragma unroll
    for (int mt = 0; mt < 2; mt++) {
        #pragma unroll
        for (int nj = 0; nj < 8; nj++) {
            int m = row0 + wm * 32 + mt * 16 + (lane >> 2);
            int n = col0 + wn * 64 + nj * 8 + (lane & 3) * 2;
            #pragma unroll
            for (int half = 0; half < 2; half++) {
                int mm = m + half * 8;
                float v0 = acc[mt][nj][half * 2 + 0];
                float v1 = acc[mt][nj][half * 2 + 1];
                if (MODE == 1) {
                    out[(size_t)mm * DMODEL + n]     = v0;
                    out[(size_t)mm * DMODEL + n + 1] = v1;
                } else {
                    #pragma unroll
                    for (int e = 0; e < 2; e++) {
                        int nn = n + e;
                        float v = e ? v1 : v0;
                        if (nn < DINNER) {
                            g_z[(size_t)mm * DINNER + nn] = v;
                        } else if (nn < DINNER + CONVDIM) {
                            g_xBC[(size_t)mm * CONVDIM + (nn - DINNER)] = v;
                        } else if (nn < DPROJ) {
                            int h = nn - (DINNER + CONVDIM);
                            g_dt[(size_t)mm * NHEADS + h] =
                                softplus_f(v + dt_bias[h]);
                        }
                    }
                }
            }
        }
    }
}

// ============================================================================
// fp16 convert kernels
// ============================================================================
__global__ void cvt_half(const float* __restrict__ src,
                         __half* __restrict__ dst, int n)
{
    int i = blockIdx.x * blockDim.x + threadIdx.x;
    if (i < n) dst[i] = __float2half(src[i]);
}

__global__ void cvt_w1_pad(const float* __restrict__ W)
{
    int i = blockIdx.x * blockDim.x + threadIdx.x;   // over NPAD1*DMODEL
    if (i >= NPAD1 * DMODEL) return;
    int r = i / DMODEL;
    float x = (r < DPROJ) ? W[(size_t)r * DMODEL + (i - r * DMODEL)] : 0.f;
    g_W1h[i] = __float2half(x);
}

// ============================================================================
// Causal depthwise conv + SiLU + split
// ============================================================================
__global__ void conv_silu_kernel(const float* __restrict__ conv_w,
                                 const float* __restrict__ conv_b)
{
    const int row = blockIdx.x;
    const int b = row / SEQ;
    const int l = row - b * SEQ;
    for (int ch = threadIdx.x; ch < CONVDIM; ch += blockDim.x) {
        float acc = conv_b[ch];
        #pragma unroll
        for (int j = 0; j < DCONV; j++) {
            int ls = l - (DCONV - 1) + j;
            if (ls >= 0)
                acc += conv_w[ch * DCONV + j] *
                       g_xBC[(size_t)(b * SEQ + ls) * CONVDIM + ch];
        }
        float v = silu_f(acc);
        if (ch < DINNER) {
            int h = ch >> 8;
            g_xh[(size_t)row * DINNER + ch] = v * g_dt[(size_t)row * NHEADS + h];
        } else if (ch < DINNER + DSTATE) {
            g_Bm[(size_t)row * DSTATE + (ch - DINNER)] = v;
        } else {
            g_Cm[(size_t)row * DSTATE + (ch - DINNER - DSTATE)] = v;
        }
    }
}

// ============================================================================
// Per-chunk states
// ============================================================================
__global__ void chunk_states_kernel(const float* __restrict__ log_A)
{
    const int id = blockIdx.x;
    const int b = id >> 9;
    const int rem = id & 511;
    const int c = rem >> 3;
    const int h = rem & 7;
    const float a = -expf(log_A[h]);

    __shared__ float Bs[CHUNKL][DSTATE];
    const int t = threadIdx.x;
    for (int i = t; i < CHUNKL * DSTATE; i += 256)
        Bs[i >> 4][i & 15] =
            g_Bm[(size_t)(b * SEQ + c * CHUNKL + (i >> 4)) * DSTATE + (i & 15)];
    __syncthreads();

    float acc[DSTATE];
    #pragma unroll
    for (int n = 0; n < DSTATE; n++) acc[n] = 0.f;

    const int p = t;
    for (int s = 0; s < CHUNKL; s++) {
        float xv = g_xh[(size_t)(b * SEQ + c * CHUNKL + s) * DINNER + h * HEADDIM + p];
        float w = expf(a * (float)(CHUNKL - 1 - s)) * xv;
        #pragma unroll
        for (int n = 0; n < DSTATE; n++) acc[n] += Bs[s][n] * w;
    }
    size_t base = ((size_t)id * HEADDIM + p) * DSTATE;
    #pragma unroll
    for (int n = 0; n < DSTATE; n++) g_states[base + n] = acc[n];
}

// ============================================================================
// Inter-chunk scan
// ============================================================================
__global__ void state_scan_kernel(const float* __restrict__ log_A)
{
    const int gid = blockIdx.x * blockDim.x + threadIdx.x;
    const int b = gid >> 15;
    const int r = gid & 32767;
    const int h = r >> 12;
    const float a = -expf(log_A[h]);
    const float d = expf(a * (float)CHUNKL);
    float P = 0.f;
    for (int c = 0; c < NCHUNK; c++) {
        size_t off = (size_t)(b * NCHUNK + c) * 32768 + r;
        g_Pst[off] = P;
        P = d * P + g_states[off];
    }
}

// ============================================================================
// SSD Y kernel
// ============================================================================
__global__ void ssd_y_kernel(const float* __restrict__ log_A,
                             const float* __restrict__ D_skip)
{
    extern __shared__ float sh[];
    float* Bs = sh;
    float* Cs = sh + 1024;
    float* G  = sh + 2048;
    float* xs = sh + 2048 + 4096;

    const int id = blockIdx.x;
    const int b = id >> 9;
    const int rem = id & 511;
    const int c = rem >> 3;
    const int h = rem & 7;
    const float a = -expf(log_A[h]);
    const int t = threadIdx.x;
    const int rowbase = b * SEQ + c * CHUNKL;

    for (int i = t; i < CHUNKL * DSTATE; i += 256) {
        size_t gi = (size_t)(rowbase + (i >> 4)) * DSTATE + (i & 15);
        Bs[i] = g_Bm[gi];
        Cs[i] = g_Cm[gi];
    }
    for (int i = t; i < CHUNKL * HEADDIM; i += 256) {
        int s = i >> 8, p = i & 255;
        xs[i] = g_xh[(size_t)(rowbase + s) * DINNER + h * HEADDIM + p];
    }
    __syncthreads();

    for (int e = t * 16; e < t * 16 + 16; e++) {
        int tt = e >> 6, ss = e & 63;
        float val = 0.f;
        if (ss <= tt) {
            float dot = 0.f;
            #pragma unroll
            for (int n = 0; n < DSTATE; n++) dot += Cs[tt * 16 + n] * Bs[ss * 16 + n];
            val = expf(a * (float)(tt - ss)) * dot;
        }
        G[e] = val;
    }
    __syncthreads();

    const int p = t;
    float Preg[DSTATE];
    size_t pbase = ((size_t)id * HEADDIM + p) * DSTATE;
    #pragma unroll
    for (int n = 0; n < DSTATE; n++) Preg[n] = g_Pst[pbase + n];
    const float dsk = D_skip[h];

    for (int tt = 0; tt < CHUNKL; tt++) {
        float acc = 0.f;
        const float* Gr = &G[tt * 64];
        for (int ss = 0; ss <= tt; ss++) acc += Gr[ss] * xs[ss * 256 + p];
        float offv = 0.f;
        #pragma unroll
        for (int n = 0; n < DSTATE; n++) offv += Cs[tt * 16 + n] * Preg[n];
        float y = acc + expf(a * (float)(tt + 1)) * offv + dsk * xs[tt * 256 + p];
        g_Y[(size_t)(rowbase + tt) * DINNER + h * HEADDIM + p] = y;
    }
}

// ============================================================================
// Gate + RMS norm; emits fp16 for GEMM2
// ============================================================================
__global__ void rms_gate_kernel(const float* __restrict__ norm_w)
{
    const int row = blockIdx.x;
    const int t = threadIdx.x;
    float v[8];
    float ss = 0.f;
    #pragma unroll
    for (int k = 0; k < 8; k++) {
        int ch = k * 256 + t;
        float Yv = g_Y[(size_t)row * DINNER + ch];
        float zv = g_z[(size_t)row * DINNER + ch];
        float val = Yv * silu_f(zv);
        v[k] = val;
        ss += val * val;
    }
    __shared__ float red[256];
    red[t] = ss;
    __syncthreads();
    for (int st = 128; st > 0; st >>= 1) {
        if (t < st) red[t] += red[t + st];
        __syncthreads();
    }
    float inv = rsqrtf(red[0] / (float)DINNER + 1e-5f);
    #pragma unroll
    for (int k = 0; k < 8; k++) {
        int ch = k * 256 + t;
        g_Yh[(size_t)row * DINNER + ch] = __float2half(v[k] * inv * norm_w[ch]);
    }
}

// ============================================================================
// Launch
// ============================================================================
extern "C" void kernel_launch(void* const* d_in, const int* in_sizes, int n_in,
                              void* d_out, int out_size)
{
    const float* input   = (const float*)d_in[0];
    const float* W_in    = (const float*)d_in[1];
    const float* conv_w  = (const float*)d_in[2];
    const float* conv_b  = (const float*)d_in[3];
    const float* dt_bias = (const float*)d_in[4];
    const float* log_A   = (const float*)d_in[5];
    const float* D_skip  = (const float*)d_in[6];
    const float* norm_w  = (const float*)d_in[7];
    const float* W_out   = (const float*)d_in[8];
    float* out = (float*)d_out;

    (void)in_sizes; (void)n_in; (void)out_size;

    const int GSMEM = 4 * STAGE_BYTES;               // 196608 B
    const int SMEM_Y = (1024 + 1024 + 4096 + 16384) * 4;
    cudaFuncSetAttribute(mma_gemm<0>, cudaFuncAttributeMaxDynamicSharedMemorySize, GSMEM);
    cudaFuncSetAttribute(mma_gemm<1>, cudaFuncAttributeMaxDynamicSharedMemorySize, GSMEM);
    cudaFuncSetAttribute(ssd_y_kernel, cudaFuncAttributeMaxDynamicSharedMemorySize, SMEM_Y);

    __half *Xh, *W2h, *Yh;
    cudaGetSymbolAddress((void**)&Xh,  g_Xh);
    cudaGetSymbolAddress((void**)&W2h, g_W2h);
    cudaGetSymbolAddress((void**)&Yh,  g_Yh);
    __half *W1h;
    cudaGetSymbolAddress((void**)&W1h, g_W1h);

    // converts
    {
        int n = NROWS * DMODEL;
        cvt_half<<<(n + 255) / 256, 256>>>(input, Xh, n);
    }
    cvt_w1_pad<<<(NPAD1 * DMODEL + 255) / 256, 256>>>(W_in);
    {
        int n = DMODEL * DINNER;
        cvt_half<<<(n + 255) / 256, 256>>>(W_out, W2h, n);
    }

    // 1) in-projection (fp16 mma)
    mma_gemm<0><<<dim3(NPAD1 / 256, NROWS / 128), 512, GSMEM>>>(
        Xh, W1h, DMODEL, nullptr, dt_bias);

    // 2) conv + silu + split
    conv_silu_kernel<<<NROWS, 256>>>(conv_w, conv_b);

    // 3) per-chunk states
    chunk_states_kernel<<<BATCH * NCHUNK * NHEADS, 256>>>(log_A);

    // 4) inter-chunk scan
    state_scan_kernel<<<(BATCH * NHEADS * HEADDIM * DSTATE) / 256, 256>>>(log_A);

    // 5) Y
    ssd_y_kernel<<<BATCH * NCHUNK * NHEADS, 256, SMEM_Y>>>(log_A, D_skip);

    // 6) gate + RMS norm (emits fp16)
    rms_gate_kernel<<<NROWS, 256>>>(norm_w);

    // 7) out-projection (fp16 mma)
    mma_gemm<1><<<dim3(DMODEL / 256, NROWS / 128), 512, GSMEM>>>(
        Yh, W2h, DINNER, out, nullptr);
}

// round 13
// speedup vs baseline: 1.5921x; 1.3144x over previous
#include <cuda_runtime.h>
#include <cuda_fp16.h>
#include <math.h>
#include <stdint.h>

// ---------------- problem constants ----------------
#define BATCH   4
#define SEQ     4096
#define DMODEL  1024
#define DSTATE  16
#define DCONV   4
#define NHEADS  8
#define CHUNKL  64
#define DINNER  2048
#define HEADDIM 256
#define CONVDIM 2080              // DINNER + 2*DSTATE
#define DPROJ   4136              // 2*DINNER + 2*DSTATE + NHEADS
#define NROWS   (BATCH*SEQ)       // 16384
#define NCHUNK  (SEQ/CHUNKL)      // 64
#define NPAD1   4352              // 17*256 padded N for GEMM1

// ---------------- scratch (static device globals) ----------------
__device__ float g_z     [NROWS*(size_t)DINNER];
__device__ float g_xBC   [NROWS*(size_t)CONVDIM];
__device__ float g_dt    [NROWS*(size_t)NHEADS];
__device__ float g_xh    [NROWS*(size_t)DINNER];
__device__ float g_Bm    [NROWS*(size_t)DSTATE];
__device__ float g_Cm    [NROWS*(size_t)DSTATE];
__device__ float g_states[(size_t)BATCH*NCHUNK*NHEADS*HEADDIM*DSTATE];
__device__ float g_Pst   [(size_t)BATCH*NCHUNK*NHEADS*HEADDIM*DSTATE];
__device__ float g_Y     [NROWS*(size_t)DINNER];

// fp16 operand buffers
__device__ __half g_Xh [NROWS*(size_t)DMODEL];
__device__ __half g_W1h[(size_t)NPAD1*DMODEL];
__device__ __half g_W2h[(size_t)DMODEL*DINNER];
__device__ __half g_Yh [NROWS*(size_t)DINNER];

__device__ __forceinline__ float softplus_f(float x) {
    return (x > 20.f) ? x : log1pf(expf(x));
}
__device__ __forceinline__ float silu_f(float x) {
    return x / (1.f + expf(-x));
}

__device__ __forceinline__ uint32_t smem_u32(const void* p) {
    uint32_t a;
    asm("{ .reg .u64 t; cvta.to.shared.u64 t, %1; cvt.u32.u64 %0, t; }"
        : "=r"(a) : "l"(p));
    return a;
}

#define CP_COMMIT() asm volatile("cp.async.commit_group;" ::: "memory")
#define CP_WAIT_N(n) asm volatile("cp.async.wait_group %0;" :: "n"(n) : "memory")

__device__ __forceinline__ void ldmat_x4(uint32_t a, uint32_t& r0, uint32_t& r1,
                                         uint32_t& r2, uint32_t& r3) {
    asm volatile("ldmatrix.sync.aligned.m8n8.x4.shared.b16 {%0,%1,%2,%3}, [%4];"
                 : "=r"(r0), "=r"(r1), "=r"(r2), "=r"(r3) : "r"(a));
}
__device__ __forceinline__ void mma_f16(float* c, uint32_t a0, uint32_t a1,
                                        uint32_t a2, uint32_t a3,
                                        uint32_t b0, uint32_t b1) {
    asm volatile(
        "mma.sync.aligned.m16n8k16.row.col.f32.f16.f16.f32 "
        "{%0,%1,%2,%3}, {%4,%5,%6,%7}, {%8,%9}, {%0,%1,%2,%3};"
        : "+f"(c[0]), "+f"(c[1]), "+f"(c[2]), "+f"(c[3])
        : "r"(a0), "r"(a1), "r"(a2), "r"(a3), "r"(b0), "r"(b1));
}

// copy a ROWSx64-fp16 tile (128B rows, SW128 swizzle) global->smem via cp.async
// 256 threads; NCH16 = rows*8 total 16B chunks
template<int NCH16>
__device__ __forceinline__ void load_tile(uint32_t sbase, const __half* g,
                                          int rowbase, int K, int k0, int tid) {
    #pragma unroll
    for (int it = 0; it < NCH16 / 256; it++) {
        int chunk = tid + it * 256;
        int row = chunk >> 3;
        int c16 = chunk & 7;
        uint32_t soff = (uint32_t)(row * 128 + c16 * 16);
        soff ^= ((soff >> 3) & 0x70);        // SW128
        const void* gp = g + (size_t)(rowbase + row) * K + k0 + c16 * 8;
        asm volatile("cp.async.cg.shared.global [%0], [%1], 16;"
                     :: "r"(sbase + soff), "l"(gp) : "memory");
    }
}

// swizzled shared address within a (rows)x64-fp16 tile
__device__ __forceinline__ uint32_t tile_addr(uint32_t base, int row, int colb) {
    uint32_t off = (uint32_t)(row * 128 + colb);
    off ^= ((off >> 3) & 0x70);
    return base + off;
}

// ============================================================================
// mma.sync fp16 GEMM (NT): C[M,Npad] = A[M,K] * B[Npad,K]^T, f32 acc.
// CTA tile 128x256, K-chunk 64, 4-stage cp.async pipeline, 256 threads
// (8 warps 2x4, warp tile 64x64), k-step fragment double buffering.
// MODE 0: in-proj epilogue; MODE 1: f32 store.
// ============================================================================
#define STAGE_BYTES 49152        // A 16KB + B 32KB
#define A_OFF       0
#define B_OFF       16384

template<int MODE>
__global__ __launch_bounds__(256, 1)
void mma_gemm(const __half* __restrict__ A, const __half* __restrict__ B,
              int K, float* __restrict__ out, const float* __restrict__ dt_bias)
{
    extern __shared__ char smem[];
    const uint32_t sb = smem_u32(smem);
    const int tid = threadIdx.x;
    const int wid = tid >> 5;
    const int lane = tid & 31;
    const int row0 = blockIdx.y * 128;
    const int col0 = blockIdx.x * 256;
    const int NC = K / 64;

    const int wm = wid >> 2;          // 0..1 : warp row (64 rows)
    const int wn = wid & 3;           // 0..3 : warp col (64 cols)

    float acc[4][8][4];               // 128 regs
    #pragma unroll
    for (int i = 0; i < 4; i++)
        #pragma unroll
        for (int j = 0; j < 8; j++)
            #pragma unroll
            for (int r = 0; r < 4; r++) acc[i][j][r] = 0.f;

    // ldmatrix lane addressing
    const int grp = lane >> 3;        // 0..3
    const int wit = lane & 7;         // 0..7
    const int a_r = wit + (grp & 1) * 8;
    const int a_c = (grp >> 1) * 16;
    const int b_r = wit + (grp >> 1) * 8;
    const int b_c = (grp & 1) * 16;

    // prologue: stages 0..2
    #pragma unroll
    for (int i = 0; i < 3; i++) {
        uint32_t stb = sb + i * STAGE_BYTES;
        load_tile<1024>(stb + A_OFF, A, row0, K, i * 64, tid);
        load_tile<2048>(stb + B_OFF, B, col0, K, i * 64, tid);
        CP_COMMIT();
    }

    uint32_t ah[2][4][4];             // [buf][mt][reg]
    uint32_t bh[2][8][2];             // [buf][nj][reg]

    for (int i = 0; i < NC; i++) {
        if (i + 3 < NC) {
            uint32_t stb = sb + ((i + 3) & 3) * STAGE_BYTES;
            load_tile<1024>(stb + A_OFF, A, row0, K, (i + 3) * 64, tid);
            load_tile<2048>(stb + B_OFF, B, col0, K, (i + 3) * 64, tid);
            CP_COMMIT();
            CP_WAIT_N(3);
        } else {
            CP_WAIT_N(0);
        }
        __syncthreads();

        const uint32_t sA = sb + (i & 3) * STAGE_BYTES + A_OFF;
        const uint32_t sB = sb + (i & 3) * STAGE_BYTES + B_OFF;

        // load ks=0 fragments into buf 0
        #pragma unroll
        for (int mt = 0; mt < 4; mt++) {
            int r = wm * 64 + mt * 16 + a_r;
            ldmat_x4(tile_addr(sA, r, a_c),
                     ah[0][mt][0], ah[0][mt][1], ah[0][mt][2], ah[0][mt][3]);
        }
        #pragma unroll
        for (int np = 0; np < 4; np++) {
            int r = wn * 64 + np * 16 + b_r;
            uint32_t t0, t1, t2, t3;
            ldmat_x4(tile_addr(sB, r, b_c), t0, t1, t2, t3);
            bh[0][2*np][0] = t0; bh[0][2*np][1] = t1;
            bh[0][2*np+1][0] = t2; bh[0][2*np+1][1] = t3;
        }

        #pragma unroll
        for (int ks = 0; ks < 4; ks++) {
            const int cur = ks & 1;
            const int nxt = cur ^ 1;
            if (ks < 3) {
                const int kb = (ks + 1) * 32;
                #pragma unroll
                for (int mt = 0; mt < 4; mt++) {
                    int r = wm * 64 + mt * 16 + a_r;
                    ldmat_x4(tile_addr(sA, r, kb + a_c),
                             ah[nxt][mt][0], ah[nxt][mt][1],
                             ah[nxt][mt][2], ah[nxt][mt][3]);
                }
                #pragma unroll
                for (int np = 0; np < 4; np++) {
                    int r = wn * 64 + np * 16 + b_r;
                    uint32_t t0, t1, t2, t3;
                    ldmat_x4(tile_addr(sB, r, kb + b_c), t0, t1, t2, t3);
                    bh[nxt][2*np][0] = t0; bh[nxt][2*np][1] = t1;
                    bh[nxt][2*np+1][0] = t2; bh[nxt][2*np+1][1] = t3;
                }
            }
            #pragma unroll
            for (int mt = 0; mt < 4; mt++)
                #pragma unroll
                for (int nj = 0; nj < 8; nj++)
                    mma_f16(acc[mt][nj],
                            ah[cur][mt][0], ah[cur][mt][1],
                            ah[cur][mt][2], ah[cur][mt][3],
                            bh[cur][nj][0], bh[cur][nj][1]);
        }
        __syncthreads();
    }

    // epilogue: direct global stores (each 4-lane quad covers a 32B sector)
    #pragma unroll
    for (int mt = 0; mt < 4; mt++) {
        #pragma unroll
        for (int nj = 0; nj < 8; nj++) {
            int m = row0 + wm * 64 + mt * 16 + (lane >> 2);
            int n = col0 + wn * 64 + nj * 8 + (lane & 3) * 2;
            #pragma unroll
            for (int half = 0; half < 2; half++) {
                int mm = m + half * 8;
                float v0 = acc[mt][nj][half * 2 + 0];
                float v1 = acc[mt][nj][half * 2 + 1];
                if (MODE == 1) {
                    out[(size_t)mm * DMODEL + n]     = v0;
                    out[(size_t)mm * DMODEL + n + 1] = v1;
                } else {
                    #pragma unroll
                    for (int e = 0; e < 2; e++) {
                        int nn = n + e;
                        float v = e ? v1 : v0;
                        if (nn < DINNER) {
                            g_z[(size_t)mm * DINNER + nn] = v;
                        } else if (nn < DINNER + CONVDIM) {
                            g_xBC[(size_t)mm * CONVDIM + (nn - DINNER)] = v;
                        } else if (nn < DPROJ) {
                            int h = nn - (DINNER + CONVDIM);
                            g_dt[(size_t)mm * NHEADS + h] =
                                softplus_f(v + dt_bias[h]);
                        }
                    }
                }
            }
        }
    }
}

// ============================================================================
// fp16 convert kernels
// ============================================================================
__global__ void cvt_half(const float* __restrict__ src,
                         __half* __restrict__ dst, int n)
{
    int i = blockIdx.x * blockDim.x + threadIdx.x;
    if (i < n) dst[i] = __float2half(src[i]);
}

__global__ void cvt_w1_pad(const float* __restrict__ W)
{
    int i = blockIdx.x * blockDim.x + threadIdx.x;   // over NPAD1*DMODEL
    if (i >= NPAD1 * DMODEL) return;
    int r = i / DMODEL;
    float x = (r < DPROJ) ? W[(size_t)r * DMODEL + (i - r * DMODEL)] : 0.f;
    g_W1h[i] = __float2half(x);
}

// ============================================================================
// Causal depthwise conv + SiLU + split
// ============================================================================
__global__ void conv_silu_kernel(const float* __restrict__ conv_w,
                                 const float* __restrict__ conv_b)
{
    const int row = blockIdx.x;
    const int b = row / SEQ;
    const int l = row - b * SEQ;
    for (int ch = threadIdx.x; ch < CONVDIM; ch += blockDim.x) {
        float acc = conv_b[ch];
        #pragma unroll
        for (int j = 0; j < DCONV; j++) {
            int ls = l - (DCONV - 1) + j;
            if (ls >= 0)
                acc += conv_w[ch * DCONV + j] *
                       g_xBC[(size_t)(b * SEQ + ls) * CONVDIM + ch];
        }
        float v = silu_f(acc);
        if (ch < DINNER) {
            int h = ch >> 8;
            g_xh[(size_t)row * DINNER + ch] = v * g_dt[(size_t)row * NHEADS + h];
        } else if (ch < DINNER + DSTATE) {
            g_Bm[(size_t)row * DSTATE + (ch - DINNER)] = v;
        } else {
            g_Cm[(size_t)row * DSTATE + (ch - DINNER - DSTATE)] = v;
        }
    }
}

// ============================================================================
// Per-chunk states
// ============================================================================
__global__ void chunk_states_kernel(const float* __restrict__ log_A)
{
    const int id = blockIdx.x;
    const int b = id >> 9;
    const int rem = id & 511;
    const int c = rem >> 3;
    const int h = rem & 7;
    const float a = -expf(log_A[h]);

    __shared__ float Bs[CHUNKL][DSTATE];
    const int t = threadIdx.x;
    for (int i = t; i < CHUNKL * DSTATE; i += 256)
        Bs[i >> 4][i & 15] =
            g_Bm[(size_t)(b * SEQ + c * CHUNKL + (i >> 4)) * DSTATE + (i & 15)];
    __syncthreads();

    float acc[DSTATE];
    #pragma unroll
    for (int n = 0; n < DSTATE; n++) acc[n] = 0.f;

    const int p = t;
    for (int s = 0; s < CHUNKL; s++) {
        float xv = g_xh[(size_t)(b * SEQ + c * CHUNKL + s) * DINNER + h * HEADDIM + p];
        float w = expf(a * (float)(CHUNKL - 1 - s)) * xv;
        #pragma unroll
        for (int n = 0; n < DSTATE; n++) acc[n] += Bs[s][n] * w;
    }
    size_t base = ((size_t)id * HEADDIM + p) * DSTATE;
    #pragma unroll
    for (int n = 0; n < DSTATE; n++) g_states[base + n] = acc[n];
}

// ============================================================================
// Inter-chunk scan
// ============================================================================
__global__ void state_scan_kernel(const float* __restrict__ log_A)
{
    const int gid = blockIdx.x * blockDim.x + threadIdx.x;
    const int b = gid >> 15;
    const int r = gid & 32767;
    const int h = r >> 12;
    const float a = -expf(log_A[h]);
    const float d = expf(a * (float)CHUNKL);
    float P = 0.f;
    for (int c = 0; c < NCHUNK; c++) {
        size_t off = (size_t)(b * NCHUNK + c) * 32768 + r;
        g_Pst[off] = P;
        P = d * P + g_states[off];
    }
}

// ============================================================================
// SSD Y kernel
// ============================================================================
__global__ void ssd_y_kernel(const float* __restrict__ log_A,
                             const float* __restrict__ D_skip)
{
    extern __shared__ float sh[];
    float* Bs = sh;
    float* Cs = sh + 1024;
    float* G  = sh + 2048;
    float* xs = sh + 2048 + 4096;

    const int id = blockIdx.x;
    const int b = id >> 9;
    const int rem = id & 511;
    const int c = rem >> 3;
    const int h = rem & 7;
    const float a = -expf(log_A[h]);
    const int t = threadIdx.x;
    const int rowbase = b * SEQ + c * CHUNKL;

    for (int i = t; i < CHUNKL * DSTATE; i += 256) {
        size_t gi = (size_t)(rowbase + (i >> 4)) * DSTATE + (i & 15);
        Bs[i] = g_Bm[gi];
        Cs[i] = g_Cm[gi];
    }
    for (int i = t; i < CHUNKL * HEADDIM; i += 256) {
        int s = i >> 8, p = i & 255;
        xs[i] = g_xh[(size_t)(rowbase + s) * DINNER + h * HEADDIM + p];
    }
    __syncthreads();

    for (int e = t * 16; e < t * 16 + 16; e++) {
        int tt = e >> 6, ss = e & 63;
        float val = 0.f;
        if (ss <= tt) {
            float dot = 0.f;
            #pragma unroll
            for (int n = 0; n < DSTATE; n++) dot += Cs[tt * 16 + n] * Bs[ss * 16 + n];
            val = expf(a * (float)(tt - ss)) * dot;
        }
        G[e] = val;
    }
    __syncthreads();

    const int p = t;
    float Preg[DSTATE];
    size_t pbase = ((size_t)id * HEADDIM + p) * DSTATE;
    #pragma unroll
    for (int n = 0; n < DSTATE; n++) Preg[n] = g_Pst[pbase + n];
    const float dsk = D_skip[h];

    for (int tt = 0; tt < CHUNKL; tt++) {
        float acc = 0.f;
        const float* Gr = &G[tt * 64];
        for (int ss = 0; ss <= tt; ss++) acc += Gr[ss] * xs[ss * 256 + p];
        float offv = 0.f;
        #pragma unroll
        for (int n = 0; n < DSTATE; n++) offv += Cs[tt * 16 + n] * Preg[n];
        float y = acc + expf(a * (float)(tt + 1)) * offv + dsk * xs[tt * 256 + p];
        g_Y[(size_t)(rowbase + tt) * DINNER + h * HEADDIM + p] = y;
    }
}

// ============================================================================
// Gate + RMS norm; emits fp16 for GEMM2
// ============================================================================
__global__ void rms_gate_kernel(const float* __restrict__ norm_w)
{
    const int row = blockIdx.x;
    const int t = threadIdx.x;
    float v[8];
    float ss = 0.f;
    #pragma unroll
    for (int k = 0; k < 8; k++) {
        int ch = k * 256 + t;
        float Yv = g_Y[(size_t)row * DINNER + ch];
        float zv = g_z[(size_t)row * DINNER + ch];
        float val = Yv * silu_f(zv);
        v[k] = val;
        ss += val * val;
    }
    __shared__ float red[256];
    red[t] = ss;
    __syncthreads();
    for (int st = 128; st > 0; st >>= 1) {
        if (t < st) red[t] += red[t + st];
        __syncthreads();
    }
    float inv = rsqrtf(red[0] / (float)DINNER + 1e-5f);
    #pragma unroll
    for (int k = 0; k < 8; k++) {
        int ch = k * 256 + t;
        g_Yh[(size_t)row * DINNER + ch] = __float2half(v[k] * inv * norm_w[ch]);
    }
}

// ============================================================================
// Launch
// ============================================================================
extern "C" void kernel_launch(void* const* d_in, const int* in_sizes, int n_in,
                              void* d_out, int out_size)
{
    const float* input   = (const float*)d_in[0];
    const float* W_in    = (const float*)d_in[1];
    const float* conv_w  = (const float*)d_in[2];
    const float* conv_b  = (const float*)d_in[3];
    const float* dt_bias = (const float*)d_in[4];
    const float* log_A   = (const float*)d_in[5];
    const float* D_skip  = (const float*)d_in[6];
    const float* norm_w  = (const float*)d_in[7];
    const float* W_out   = (const float*)d_in[8];
    float* out = (float*)d_out;

    (void)in_sizes; (void)n_in; (void)out_size;

    const int GSMEM = 4 * STAGE_BYTES;               // 196608 B
    const int SMEM_Y = (1024 + 1024 + 4096 + 16384) * 4;
    cudaFuncSetAttribute(mma_gemm<0>, cudaFuncAttributeMaxDynamicSharedMemorySize, GSMEM);
    cudaFuncSetAttribute(mma_gemm<1>, cudaFuncAttributeMaxDynamicSharedMemorySize, GSMEM);
    cudaFuncSetAttribute(ssd_y_kernel, cudaFuncAttributeMaxDynamicSharedMemorySize, SMEM_Y);

    __half *Xh, *W2h, *Yh, *W1h;
    cudaGetSymbolAddress((void**)&Xh,  g_Xh);
    cudaGetSymbolAddress((void**)&W2h, g_W2h);
    cudaGetSymbolAddress((void**)&Yh,  g_Yh);
    cudaGetSymbolAddress((void**)&W1h, g_W1h);

    // converts
    {
        int n = NROWS * DMODEL;
        cvt_half<<<(n + 255) / 256, 256>>>(input, Xh, n);
    }
    cvt_w1_pad<<<(NPAD1 * DMODEL + 255) / 256, 256>>>(W_in);
    {
        int n = DMODEL * DINNER;
        cvt_half<<<(n + 255) / 256, 256>>>(W_out, W2h, n);
    }

    // 1) in-projection (fp16 mma)
    mma_gemm<0><<<dim3(NPAD1 / 256, NROWS / 128), 256, GSMEM>>>(
        Xh, W1h, DMODEL, nullptr, dt_bias);

    // 2) conv + silu + split
    conv_silu_kernel<<<NROWS, 256>>>(conv_w, conv_b);

    // 3) per-chunk states
    chunk_states_kernel<<<BATCH * NCHUNK * NHEADS, 256>>>(log_A);

    // 4) inter-chunk scan
    state_scan_kernel<<<(BATCH * NHEADS * HEADDIM * DSTATE) / 256, 256>>>(log_A);

    // 5) Y
    ssd_y_kernel<<<BATCH * NCHUNK * NHEADS, 256, SMEM_Y>>>(log_A, D_skip);

    // 6) gate + RMS norm (emits fp16)
    rms_gate_kernel<<<NROWS, 256>>>(norm_w);

    // 7) out-projection (fp16 mma)
    mma_gemm<1><<<dim3(DMODEL / 256, NROWS / 128), 256, GSMEM>>>(
        Yh, W2h, DINNER, out, nullptr);
}

// round 14
// speedup vs baseline: 1.6972x; 1.0660x over previous
#include <cuda_runtime.h>
#include <cuda_fp16.h>
#include <math.h>
#include <stdint.h>

// ---------------- problem constants ----------------
#define BATCH   4
#define SEQ     4096
#define DMODEL  1024
#define DSTATE  16
#define DCONV   4
#define NHEADS  8
#define CHUNKL  64
#define DINNER  2048
#define HEADDIM 256
#define CONVDIM 2080              // DINNER + 2*DSTATE
#define DPROJ   4136              // 2*DINNER + 2*DSTATE + NHEADS
#define NROWS   (BATCH*SEQ)       // 16384
#define NCHUNK  (SEQ/CHUNKL)      // 64
#define NPAD1   4352              // 17*256 padded N for GEMM1

// ---------------- scratch (static device globals) ----------------
__device__ float g_z     [NROWS*(size_t)DINNER];
__device__ float g_xBC   [NROWS*(size_t)CONVDIM];
__device__ float g_dt    [NROWS*(size_t)NHEADS];
__device__ float g_xh    [NROWS*(size_t)DINNER];
__device__ float g_Bm    [NROWS*(size_t)DSTATE];
__device__ float g_Cm    [NROWS*(size_t)DSTATE];
__device__ float g_states[(size_t)BATCH*NCHUNK*NHEADS*HEADDIM*DSTATE];
__device__ float g_Pst   [(size_t)BATCH*NCHUNK*NHEADS*HEADDIM*DSTATE];
__device__ float g_Y     [NROWS*(size_t)DINNER];

// fp16 operand buffers
__device__ __half g_Xh [NROWS*(size_t)DMODEL];
__device__ __half g_W1h[(size_t)NPAD1*DMODEL];
__device__ __half g_W2h[(size_t)DMODEL*DINNER];
__device__ __half g_Yh [NROWS*(size_t)DINNER];

__device__ __forceinline__ float softplus_f(float x) {
    return (x > 20.f) ? x : log1pf(expf(x));
}
__device__ __forceinline__ float silu_f(float x) {
    return x / (1.f + expf(-x));
}

__device__ __forceinline__ uint32_t smem_u32(const void* p) {
    uint32_t a;
    asm("{ .reg .u64 t; cvta.to.shared.u64 t, %1; cvt.u32.u64 %0, t; }"
        : "=r"(a) : "l"(p));
    return a;
}

#define CP_COMMIT() asm volatile("cp.async.commit_group;" ::: "memory")
#define CP_WAIT_N(n) asm volatile("cp.async.wait_group %0;" :: "n"(n) : "memory")

__device__ __forceinline__ void ldmat_x4(uint32_t a, uint32_t& r0, uint32_t& r1,
                                         uint32_t& r2, uint32_t& r3) {
    asm volatile("ldmatrix.sync.aligned.m8n8.x4.shared.b16 {%0,%1,%2,%3}, [%4];"
                 : "=r"(r0), "=r"(r1), "=r"(r2), "=r"(r3) : "r"(a));
}
__device__ __forceinline__ void mma_f16(float* c, uint32_t a0, uint32_t a1,
                                        uint32_t a2, uint32_t a3,
                                        uint32_t b0, uint32_t b1) {
    asm volatile(
        "mma.sync.aligned.m16n8k16.row.col.f32.f16.f16.f32 "
        "{%0,%1,%2,%3}, {%4,%5,%6,%7}, {%8,%9}, {%0,%1,%2,%3};"
        : "+f"(c[0]), "+f"(c[1]), "+f"(c[2]), "+f"(c[3])
        : "r"(a0), "r"(a1), "r"(a2), "r"(a3), "r"(b0), "r"(b1));
}

// copy a ROWSx64-fp16 tile (128B rows, SW128 swizzle) global->smem via cp.async
// 256 threads; NCH16 = rows*8 total 16B chunks
template<int NCH16>
__device__ __forceinline__ void load_tile(uint32_t sbase, const __half* g,
                                          int rowbase, int K, int k0, int tid) {
    #pragma unroll
    for (int it = 0; it < NCH16 / 256; it++) {
        int chunk = tid + it * 256;
        int row = chunk >> 3;
        int c16 = chunk & 7;
        uint32_t soff = (uint32_t)(row * 128 + c16 * 16);
        soff ^= ((soff >> 3) & 0x70);        // SW128
        const void* gp = g + (size_t)(rowbase + row) * K + k0 + c16 * 8;
        asm volatile("cp.async.cg.shared.global [%0], [%1], 16;"
                     :: "r"(sbase + soff), "l"(gp) : "memory");
    }
}

// swizzled shared address within a (rows)x64-fp16 tile
__device__ __forceinline__ uint32_t tile_addr(uint32_t base, int row, int colb) {
    uint32_t off = (uint32_t)(row * 128 + colb);
    off ^= ((off >> 3) & 0x70);
    return base + off;
}

// ============================================================================
// mma.sync fp16 GEMM (NT): C[M,Npad] = A[M,K] * B[Npad,K]^T, f32 acc.
// CTA tile 128x256, K-chunk 128 (2x 64-col subtiles), 2-stage cp.async double
// buffer, 256 threads (8 warps 2x4, warp tile 64x64), k-step fragment double
// buffering. MODE 0: in-proj epilogue; MODE 1: f32 store.
// ============================================================================
#define STAGE_BYTES 98304        // A 32KB (2 subtiles) + B 64KB (2 subtiles)
#define A_OFF       0
#define B_OFF       32768

template<int MODE>
__global__ __launch_bounds__(256, 1)
void mma_gemm(const __half* __restrict__ A, const __half* __restrict__ B,
              int K, float* __restrict__ out, const float* __restrict__ dt_bias)
{
    extern __shared__ char smem[];
    const uint32_t sb = smem_u32(smem);
    const int tid = threadIdx.x;
    const int wid = tid >> 5;
    const int lane = tid & 31;
    const int row0 = blockIdx.y * 128;
    const int col0 = blockIdx.x * 256;
    const int NC = K / 128;

    const int wm = wid >> 2;          // 0..1 : warp row (64 rows)
    const int wn = wid & 3;           // 0..3 : warp col (64 cols)

    float acc[4][8][4];               // 128 regs
    #pragma unroll
    for (int i = 0; i < 4; i++)
        #pragma unroll
        for (int j = 0; j < 8; j++)
            #pragma unroll
            for (int r = 0; r < 4; r++) acc[i][j][r] = 0.f;

    // ldmatrix lane addressing
    const int grp = lane >> 3;        // 0..3
    const int wit = lane & 7;         // 0..7
    const int a_r = wit + (grp & 1) * 8;
    const int a_c = (grp >> 1) * 16;
    const int b_r = wit + (grp >> 1) * 8;
    const int b_c = (grp & 1) * 16;

    // prologue: chunk 0 -> stage 0 (two 64-col subtiles per operand)
    load_tile<1024>(sb + A_OFF,         A, row0, K, 0,  tid);
    load_tile<1024>(sb + A_OFF + 16384, A, row0, K, 64, tid);
    load_tile<2048>(sb + B_OFF,         B, col0, K, 0,  tid);
    load_tile<2048>(sb + B_OFF + 32768, B, col0, K, 64, tid);
    CP_COMMIT();

    uint32_t ah[2][4][4];             // [buf][mt][reg]
    uint32_t bh[2][8][2];             // [buf][nj][reg]

    for (int i = 0; i < NC; i++) {
        if (i + 1 < NC) {
            uint32_t stb = sb + ((i + 1) & 1) * STAGE_BYTES;
            int k0 = (i + 1) * 128;
            load_tile<1024>(stb + A_OFF,         A, row0, K, k0,      tid);
            load_tile<1024>(stb + A_OFF + 16384, A, row0, K, k0 + 64, tid);
            load_tile<2048>(stb + B_OFF,         B, col0, K, k0,      tid);
            load_tile<2048>(stb + B_OFF + 32768, B, col0, K, k0 + 64, tid);
            CP_COMMIT();
            CP_WAIT_N(1);
        } else {
            CP_WAIT_N(0);
        }
        __syncthreads();

        const uint32_t sA = sb + (i & 1) * STAGE_BYTES + A_OFF;
        const uint32_t sB = sb + (i & 1) * STAGE_BYTES + B_OFF;

        // load ks=0 fragments into buf 0 (subtile 0, kb=0)
        #pragma unroll
        for (int mt = 0; mt < 4; mt++) {
            int r = wm * 64 + mt * 16 + a_r;
            ldmat_x4(tile_addr(sA, r, a_c),
                     ah[0][mt][0], ah[0][mt][1], ah[0][mt][2], ah[0][mt][3]);
        }
        #pragma unroll
        for (int np = 0; np < 4; np++) {
            int r = wn * 64 + np * 16 + b_r;
            uint32_t t0, t1, t2, t3;
            ldmat_x4(tile_addr(sB, r, b_c), t0, t1, t2, t3);
            bh[0][2*np][0] = t0; bh[0][2*np][1] = t1;
            bh[0][2*np+1][0] = t2; bh[0][2*np+1][1] = t3;
        }

        #pragma unroll
        for (int ks = 0; ks < 8; ks++) {
            const int cur = ks & 1;
            const int nxt = cur ^ 1;
            if (ks < 7) {
                const int kn = ks + 1;
                const uint32_t sAs = sA + (kn >> 2) * 16384;
                const uint32_t sBs = sB + (kn >> 2) * 32768;
                const int kb = (kn & 3) * 32;
                #pragma unroll
                for (int mt = 0; mt < 4; mt++) {
                    int r = wm * 64 + mt * 16 + a_r;
                    ldmat_x4(tile_addr(sAs, r, kb + a_c),
                             ah[nxt][mt][0], ah[nxt][mt][1],
                             ah[nxt][mt][2], ah[nxt][mt][3]);
                }
                #pragma unroll
                for (int np = 0; np < 4; np++) {
                    int r = wn * 64 + np * 16 + b_r;
                    uint32_t t0, t1, t2, t3;
                    ldmat_x4(tile_addr(sBs, r, kb + b_c), t0, t1, t2, t3);
                    bh[nxt][2*np][0] = t0; bh[nxt][2*np][1] = t1;
                    bh[nxt][2*np+1][0] = t2; bh[nxt][2*np+1][1] = t3;
                }
            }
            #pragma unroll
            for (int mt = 0; mt < 4; mt++)
                #pragma unroll
                for (int nj = 0; nj < 8; nj++)
                    mma_f16(acc[mt][nj],
                            ah[cur][mt][0], ah[cur][mt][1],
                            ah[cur][mt][2], ah[cur][mt][3],
                            bh[cur][nj][0], bh[cur][nj][1]);
        }
        __syncthreads();
    }

    // epilogue: direct global stores (each 4-lane quad covers a 32B sector)
    #pragma unroll
    for (int mt = 0; mt < 4; mt++) {
        #pragma unroll
        for (int nj = 0; nj < 8; nj++) {
            int m = row0 + wm * 64 + mt * 16 + (lane >> 2);
            int n = col0 + wn * 64 + nj * 8 + (lane & 3) * 2;
            #pragma unroll
            for (int half = 0; half < 2; half++) {
                int mm = m + half * 8;
                float v0 = acc[mt][nj][half * 2 + 0];
                float v1 = acc[mt][nj][half * 2 + 1];
                if (MODE == 1) {
                    out[(size_t)mm * DMODEL + n]     = v0;
                    out[(size_t)mm * DMODEL + n + 1] = v1;
                } else {
                    #pragma unroll
                    for (int e = 0; e < 2; e++) {
                        int nn = n + e;
                        float v = e ? v1 : v0;
                        if (nn < DINNER) {
                            g_z[(size_t)mm * DINNER + nn] = v;
                        } else if (nn < DINNER + CONVDIM) {
                            g_xBC[(size_t)mm * CONVDIM + (nn - DINNER)] = v;
                        } else if (nn < DPROJ) {
                            int h = nn - (DINNER + CONVDIM);
                            g_dt[(size_t)mm * NHEADS + h] =
                                softplus_f(v + dt_bias[h]);
                        }
                    }
                }
            }
        }
    }
}

// ============================================================================
// fp16 convert kernels
// ============================================================================
__global__ void cvt_half(const float* __restrict__ src,
                         __half* __restrict__ dst, int n)
{
    int i = blockIdx.x * blockDim.x + threadIdx.x;
    if (i < n) dst[i] = __float2half(src[i]);
}

__global__ void cvt_w1_pad(const float* __restrict__ W)
{
    int i = blockIdx.x * blockDim.x + threadIdx.x;   // over NPAD1*DMODEL
    if (i >= NPAD1 * DMODEL) return;
    int r = i / DMODEL;
    float x = (r < DPROJ) ? W[(size_t)r * DMODEL + (i - r * DMODEL)] : 0.f;
    g_W1h[i] = __float2half(x);
}

// ============================================================================
// Causal depthwise conv + SiLU + split — sliding-window registers.
// grid (BATCH*32 tiles of 128 rows, 8 ch-blocks), 260 threads (8*260=2080).
// ============================================================================
__device__ __forceinline__ void conv_store(int row, int ch, int hh, float v)
{
    if (ch < DINNER) {
        g_xh[(size_t)row * DINNER + ch] = v * g_dt[(size_t)row * NHEADS + hh];
    } else if (ch < DINNER + DSTATE) {
        g_Bm[(size_t)row * DSTATE + (ch - DINNER)] = v;
    } else {
        g_Cm[(size_t)row * DSTATE + (ch - DINNER - DSTATE)] = v;
    }
}

__global__ void conv_silu_kernel(const float* __restrict__ conv_w,
                                 const float* __restrict__ conv_b)
{
    const int ch = blockIdx.y * 260 + threadIdx.x;   // 0..2079
    const int bt = blockIdx.x;
    const int b = bt >> 5;
    const int tile = bt & 31;
    const int l0 = tile * 128;
    const int hh = ch >> 8;

    const float w0 = conv_w[ch * 4 + 0];
    const float w1 = conv_w[ch * 4 + 1];
    const float w2 = conv_w[ch * 4 + 2];
    const float w3 = conv_w[ch * 4 + 3];
    const float cb = conv_b[ch];

    const size_t base = (size_t)(b * SEQ) * CONVDIM + ch;

    float xm3 = 0.f, xm2 = 0.f, xm1 = 0.f;
    if (l0 > 0) {
        xm3 = g_xBC[base + (size_t)(l0 - 3) * CONVDIM];
        xm2 = g_xBC[base + (size_t)(l0 - 2) * CONVDIM];
        xm1 = g_xBC[base + (size_t)(l0 - 1) * CONVDIM];
    }

    for (int r = 0; r < 128; r += 4) {
        const int l = l0 + r;
        float x0 = g_xBC[base + (size_t)(l + 0) * CONVDIM];
        float x1 = g_xBC[base + (size_t)(l + 1) * CONVDIM];
        float x2 = g_xBC[base + (size_t)(l + 2) * CONVDIM];
        float x3 = g_xBC[base + (size_t)(l + 3) * CONVDIM];

        float v0 = silu_f(cb + w0 * xm3 + w1 * xm2 + w2 * xm1 + w3 * x0);
        float v1 = silu_f(cb + w0 * xm2 + w1 * xm1 + w2 * x0  + w3 * x1);
        float v2 = silu_f(cb + w0 * xm1 + w1 * x0  + w2 * x1  + w3 * x2);
        float v3 = silu_f(cb + w0 * x0  + w1 * x1  + w2 * x2  + w3 * x3);

        const int row = b * SEQ + l;
        conv_store(row + 0, ch, hh, v0);
        conv_store(row + 1, ch, hh, v1);
        conv_store(row + 2, ch, hh, v2);
        conv_store(row + 3, ch, hh, v3);

        xm3 = x1; xm2 = x2; xm1 = x3;
    }
}

// ============================================================================
// Per-chunk states
// ============================================================================
__global__ void chunk_states_kernel(const float* __restrict__ log_A)
{
    const int id = blockIdx.x;
    const int b = id >> 9;
    const int rem = id & 511;
    const int c = rem >> 3;
    const int h = rem & 7;
    const float a = -expf(log_A[h]);

    __shared__ float Bs[CHUNKL][DSTATE];
    const int t = threadIdx.x;
    for (int i = t; i < CHUNKL * DSTATE; i += 256)
        Bs[i >> 4][i & 15] =
            g_Bm[(size_t)(b * SEQ + c * CHUNKL + (i >> 4)) * DSTATE + (i & 15)];
    __syncthreads();

    float acc[DSTATE];
    #pragma unroll
    for (int n = 0; n < DSTATE; n++) acc[n] = 0.f;

    const int p = t;
    for (int s = 0; s < CHUNKL; s++) {
        float xv = g_xh[(size_t)(b * SEQ + c * CHUNKL + s) * DINNER + h * HEADDIM + p];
        float w = expf(a * (float)(CHUNKL - 1 - s)) * xv;
        #pragma unroll
        for (int n = 0; n < DSTATE; n++) acc[n] += Bs[s][n] * w;
    }
    size_t base = ((size_t)id * HEADDIM + p) * DSTATE;
    #pragma unroll
    for (int n = 0; n < DSTATE; n++) g_states[base + n] = acc[n];
}

// ============================================================================
// Inter-chunk scan
// ============================================================================
__global__ void state_scan_kernel(const float* __restrict__ log_A)
{
    const int gid = blockIdx.x * blockDim.x + threadIdx.x;
    const int b = gid >> 15;
    const int r = gid & 32767;
    const int h = r >> 12;
    const float a = -expf(log_A[h]);
    const float d = expf(a * (float)CHUNKL);
    float P = 0.f;
    for (int c = 0; c < NCHUNK; c++) {
        size_t off = (size_t)(b * NCHUNK + c) * 32768 + r;
        g_Pst[off] = P;
        P = d * P + g_states[off];
    }
}

// ============================================================================
// SSD Y kernel — float4 G rows + 4-row tt blocking
// ============================================================================
__global__ void ssd_y_kernel(const float* __restrict__ log_A,
                             const float* __restrict__ D_skip)
{
    extern __shared__ float sh[];
    float* Bs = sh;                   // 64*16
    float* Cs = sh + 1024;            // 64*16
    float* G  = sh + 2048;            // 64*64
    float* xs = sh + 6144;            // 64*256

    const int id = blockIdx.x;
    const int b = id >> 9;
    const int rem = id & 511;
    const int c = rem >> 3;
    const int h = rem & 7;
    const float a = -expf(log_A[h]);
    const int t = threadIdx.x;
    const int rowbase = b * SEQ + c * CHUNKL;

    for (int i = t; i < CHUNKL * DSTATE; i += 256) {
        size_t gi = (size_t)(rowbase + (i >> 4)) * DSTATE + (i & 15);
        Bs[i] = g_Bm[gi];
        Cs[i] = g_Cm[gi];
    }
    for (int i = t; i < CHUNKL * HEADDIM; i += 256) {
        int s = i >> 8, p = i & 255;
        xs[i] = g_xh[(size_t)(rowbase + s) * DINNER + h * HEADDIM + p];
    }
    __syncthreads();

    // G[tt][ss] = exp(a(tt-ss)) * (C_tt . B_ss) for ss<=tt, else 0
    for (int e = t * 16; e < t * 16 + 16; e++) {
        int tt = e >> 6, ss = e & 63;
        float val = 0.f;
        if (ss <= tt) {
            float dot = 0.f;
            #pragma unroll
            for (int n = 0; n < DSTATE; n++) dot += Cs[tt * 16 + n] * Bs[ss * 16 + n];
            val = expf(a * (float)(tt - ss)) * dot;
        }
        G[e] = val;
    }
    __syncthreads();

    const int p = t;
    float Preg[DSTATE];
    size_t pbase = ((size_t)id * HEADDIM + p) * DSTATE;
    #pragma unroll
    for (int n = 0; n < DSTATE; n++) Preg[n] = g_Pst[pbase + n];
    const float dsk = D_skip[h];

    for (int tt0 = 0; tt0 < CHUNKL; tt0 += 4) {
        float aq[4] = {0.f, 0.f, 0.f, 0.f};
        const int smax = tt0 + 4;     // G zero-padded above diagonal
        for (int ss = 0; ss < smax; ss += 4) {
            float xv0 = xs[(ss + 0) * 256 + p];
            float xv1 = xs[(ss + 1) * 256 + p];
            float xv2 = xs[(ss + 2) * 256 + p];
            float xv3 = xs[(ss + 3) * 256 + p];
            #pragma unroll
            for (int q = 0; q < 4; q++) {
                float4 g4 = *(const float4*)&G[(tt0 + q) * 64 + ss];
                aq[q] += g4.x * xv0 + g4.y * xv1 + g4.z * xv2 + g4.w * xv3;
            }
        }
        #pragma unroll
        for (int q = 0; q < 4; q++) {
            const int tt = tt0 + q;
            float offv = 0.f;
            const float4* c4 = (const float4*)&Cs[tt * 16];
            #pragma unroll
            for (int n4 = 0; n4 < 4; n4++) {
                float4 cv = c4[n4];
                offv += cv.x * Preg[n4 * 4 + 0] + cv.y * Preg[n4 * 4 + 1] +
                        cv.z * Preg[n4 * 4 + 2] + cv.w * Preg[n4 * 4 + 3];
            }
            float y = aq[q] + expf(a * (float)(tt + 1)) * offv +
                      dsk * xs[tt * 256 + p];
            g_Y[(size_t)(rowbase + tt) * DINNER + h * HEADDIM + p] = y;
        }
    }
}

// ============================================================================
// Gate + RMS norm; emits fp16 for GEMM2
// ============================================================================
__global__ void rms_gate_kernel(const float* __restrict__ norm_w)
{
    const int row = blockIdx.x;
    const int t = threadIdx.x;
    float v[8];
    float ss = 0.f;
    #pragma unroll
    for (int k = 0; k < 8; k++) {
        int ch = k * 256 + t;
        float Yv = g_Y[(size_t)row * DINNER + ch];
        float zv = g_z[(size_t)row * DINNER + ch];
        float val = Yv * silu_f(zv);
        v[k] = val;
        ss += val * val;
    }
    __shared__ float red[256];
    red[t] = ss;
    __syncthreads();
    for (int st = 128; st > 0; st >>= 1) {
        if (t < st) red[t] += red[t + st];
        __syncthreads();
    }
    float inv = rsqrtf(red[0] / (float)DINNER + 1e-5f);
    #pragma unroll
    for (int k = 0; k < 8; k++) {
        int ch = k * 256 + t;
        g_Yh[(size_t)row * DINNER + ch] = __float2half(v[k] * inv * norm_w[ch]);
    }
}

// ============================================================================
// Launch
// ============================================================================
extern "C" void kernel_launch(void* const* d_in, const int* in_sizes, int n_in,
                              void* d_out, int out_size)
{
    const float* input   = (const float*)d_in[0];
    const float* W_in    = (const float*)d_in[1];
    const float* conv_w  = (const float*)d_in[2];
    const float* conv_b  = (const float*)d_in[3];
    const float* dt_bias = (const float*)d_in[4];
    const float* log_A   = (const float*)d_in[5];
    const float* D_skip  = (const float*)d_in[6];
    const float* norm_w  = (const float*)d_in[7];
    const float* W_out   = (const float*)d_in[8];
    float* out = (float*)d_out;

    (void)in_sizes; (void)n_in; (void)out_size;

    const int GSMEM = 2 * STAGE_BYTES;               // 196608 B
    const int SMEM_Y = (1024 + 1024 + 4096 + 16384) * 4;
    cudaFuncSetAttribute(mma_gemm<0>, cudaFuncAttributeMaxDynamicSharedMemorySize, GSMEM);
    cudaFuncSetAttribute(mma_gemm<1>, cudaFuncAttributeMaxDynamicSharedMemorySize, GSMEM);
    cudaFuncSetAttribute(ssd_y_kernel, cudaFuncAttributeMaxDynamicSharedMemorySize, SMEM_Y);

    __half *Xh, *W2h, *Yh, *W1h;
    cudaGetSymbolAddress((void**)&Xh,  g_Xh);
    cudaGetSymbolAddress((void**)&W2h, g_W2h);
    cudaGetSymbolAddress((void**)&Yh,  g_Yh);
    cudaGetSymbolAddress((void**)&W1h, g_W1h);

    // converts
    {
        int n = NROWS * DMODEL;
        cvt_half<<<(n + 255) / 256, 256>>>(input, Xh, n);
    }
    cvt_w1_pad<<<(NPAD1 * DMODEL + 255) / 256, 256>>>(W_in);
    {
        int n = DMODEL * DINNER;
        cvt_half<<<(n + 255) / 256, 256>>>(W_out, W2h, n);
    }

    // 1) in-projection (fp16 mma, k128 chunks)
    mma_gemm<0><<<dim3(NPAD1 / 256, NROWS / 128), 256, GSMEM>>>(
        Xh, W1h, DMODEL, nullptr, dt_bias);

    // 2) conv + silu + split (sliding window)
    conv_silu_kernel<<<dim3(BATCH * 32, 8), 260>>>(conv_w, conv_b);

    // 3) per-chunk states
    chunk_states_kernel<<<BATCH * NCHUNK * NHEADS, 256>>>(log_A);

    // 4) inter-chunk scan
    state_scan_kernel<<<(BATCH * NHEADS * HEADDIM * DSTATE) / 256, 256>>>(log_A);

    // 5) Y (vectorized)
    ssd_y_kernel<<<BATCH * NCHUNK * NHEADS, 256, SMEM_Y>>>(log_A, D_skip);

    // 6) gate + RMS norm (emits fp16)
    rms_gate_kernel<<<NROWS, 256>>>(norm_w);

    // 7) out-projection (fp16 mma, k128 chunks)
    mma_gemm<1><<<dim3(DMODEL / 256, NROWS / 128), 256, GSMEM>>>(
        Yh, W2h, DINNER, out, nullptr);
}

// round 15
// speedup vs baseline: 2.1023x; 1.2387x over previous
#include <cuda_runtime.h>
#include <cuda_fp16.h>
#include <math.h>
#include <stdint.h>

// ---------------- problem constants ----------------
#define BATCH   4
#define SEQ     4096
#define DMODEL  1024
#define DSTATE  16
#define DCONV   4
#define NHEADS  8
#define CHUNKL  64
#define DINNER  2048
#define HEADDIM 256
#define CONVDIM 2080              // DINNER + 2*DSTATE
#define DPROJ   4136              // 2*DINNER + 2*DSTATE + NHEADS
#define NROWS   (BATCH*SEQ)       // 16384
#define NCHUNK  (SEQ/CHUNKL)      // 64
#define NPAD1   4352              // 17*256 padded N for GEMM1

// ---------------- scratch (static device globals) ----------------
__device__ __half g_z    [NROWS*(size_t)DINNER];
__device__ __half g_xBC  [NROWS*(size_t)CONVDIM];
__device__ float  g_dt   [NROWS*(size_t)NHEADS];
__device__ __half g_xh   [NROWS*(size_t)DINNER];
__device__ float  g_Bm   [NROWS*(size_t)DSTATE];
__device__ float  g_Cm   [NROWS*(size_t)DSTATE];
__device__ float  g_states[(size_t)BATCH*NCHUNK*NHEADS*HEADDIM*DSTATE];
__device__ float  g_Pst  [(size_t)BATCH*NCHUNK*NHEADS*HEADDIM*DSTATE];
__device__ __half g_Y    [NROWS*(size_t)DINNER];

// fp16 operand buffers
__device__ __half g_Xh [NROWS*(size_t)DMODEL];
__device__ __half g_W1h[(size_t)NPAD1*DMODEL];
__device__ __half g_W2h[(size_t)DMODEL*DINNER];
__device__ __half g_Yh [NROWS*(size_t)DINNER];

__device__ __forceinline__ float softplus_f(float x) {
    return (x > 20.f) ? x : log1pf(expf(x));
}
__device__ __forceinline__ float silu_f(float x) {
    return x / (1.f + expf(-x));
}

__device__ __forceinline__ uint32_t smem_u32(const void* p) {
    uint32_t a;
    asm("{ .reg .u64 t; cvta.to.shared.u64 t, %1; cvt.u32.u64 %0, t; }"
        : "=r"(a) : "l"(p));
    return a;
}

#define CP_COMMIT() asm volatile("cp.async.commit_group;" ::: "memory")
#define CP_WAIT_N(n) asm volatile("cp.async.wait_group %0;" :: "n"(n) : "memory")

__device__ __forceinline__ void ldmat_x4(uint32_t a, uint32_t& r0, uint32_t& r1,
                                         uint32_t& r2, uint32_t& r3) {
    asm volatile("ldmatrix.sync.aligned.m8n8.x4.shared.b16 {%0,%1,%2,%3}, [%4];"
                 : "=r"(r0), "=r"(r1), "=r"(r2), "=r"(r3) : "r"(a));
}
__device__ __forceinline__ void mma_f16(float* c, uint32_t a0, uint32_t a1,
                                        uint32_t a2, uint32_t a3,
                                        uint32_t b0, uint32_t b1) {
    asm volatile(
        "mma.sync.aligned.m16n8k16.row.col.f32.f16.f16.f32 "
        "{%0,%1,%2,%3}, {%4,%5,%6,%7}, {%8,%9}, {%0,%1,%2,%3};"
        : "+f"(c[0]), "+f"(c[1]), "+f"(c[2]), "+f"(c[3])
        : "r"(a0), "r"(a1), "r"(a2), "r"(a3), "r"(b0), "r"(b1));
}

// copy a ROWSx64-fp16 tile (128B rows, SW128 swizzle) global->smem via cp.async
template<int NCH16>
__device__ __forceinline__ void load_tile(uint32_t sbase, const __half* g,
                                          int rowbase, int K, int k0, int tid) {
    #pragma unroll
    for (int it = 0; it < NCH16 / 256; it++) {
        int chunk = tid + it * 256;
        int row = chunk >> 3;
        int c16 = chunk & 7;
        uint32_t soff = (uint32_t)(row * 128 + c16 * 16);
        soff ^= ((soff >> 3) & 0x70);        // SW128
        const void* gp = g + (size_t)(rowbase + row) * K + k0 + c16 * 8;
        asm volatile("cp.async.cg.shared.global [%0], [%1], 16;"
                     :: "r"(sbase + soff), "l"(gp) : "memory");
    }
}

__device__ __forceinline__ uint32_t tile_addr(uint32_t base, int row, int colb) {
    uint32_t off = (uint32_t)(row * 128 + colb);
    off ^= ((off >> 3) & 0x70);
    return base + off;
}

// ============================================================================
// mma.sync fp16 GEMM (NT): CTA tile 128x256, K-chunk 128, 2-stage double
// buffer, 256 threads (8 warps 2x4, warp tile 64x64), frag double buffering.
// MODE 0: in-proj epilogue (half2 z/xBC, f32 dt); MODE 1: f32 store.
// ============================================================================
#define STAGE_BYTES 98304        // A 32KB (2 subtiles) + B 64KB (2 subtiles)
#define A_OFF       0
#define B_OFF       32768

template<int MODE>
__global__ __launch_bounds__(256, 1)
void mma_gemm(const __half* __restrict__ A, const __half* __restrict__ B,
              int K, float* __restrict__ out, const float* __restrict__ dt_bias)
{
    extern __shared__ char smem[];
    const uint32_t sb = smem_u32(smem);
    const int tid = threadIdx.x;
    const int wid = tid >> 5;
    const int lane = tid & 31;
    const int row0 = blockIdx.y * 128;
    const int col0 = blockIdx.x * 256;
    const int NC = K / 128;

    const int wm = wid >> 2;
    const int wn = wid & 3;

    float acc[4][8][4];
    #pragma unroll
    for (int i = 0; i < 4; i++)
        #pragma unroll
        for (int j = 0; j < 8; j++)
            #pragma unroll
            for (int r = 0; r < 4; r++) acc[i][j][r] = 0.f;

    const int grp = lane >> 3;
    const int wit = lane & 7;
    const int a_r = wit + (grp & 1) * 8;
    const int a_c = (grp >> 1) * 16;
    const int b_r = wit + (grp >> 1) * 8;
    const int b_c = (grp & 1) * 16;

    load_tile<1024>(sb + A_OFF,         A, row0, K, 0,  tid);
    load_tile<1024>(sb + A_OFF + 16384, A, row0, K, 64, tid);
    load_tile<2048>(sb + B_OFF,         B, col0, K, 0,  tid);
    load_tile<2048>(sb + B_OFF + 32768, B, col0, K, 64, tid);
    CP_COMMIT();

    uint32_t ah[2][4][4];
    uint32_t bh[2][8][2];

    for (int i = 0; i < NC; i++) {
        if (i + 1 < NC) {
            uint32_t stb = sb + ((i + 1) & 1) * STAGE_BYTES;
            int k0 = (i + 1) * 128;
            load_tile<1024>(stb + A_OFF,         A, row0, K, k0,      tid);
            load_tile<1024>(stb + A_OFF + 16384, A, row0, K, k0 + 64, tid);
            load_tile<2048>(stb + B_OFF,         B, col0, K, k0,      tid);
            load_tile<2048>(stb + B_OFF + 32768, B, col0, K, k0 + 64, tid);
            CP_COMMIT();
            CP_WAIT_N(1);
        } else {
            CP_WAIT_N(0);
        }
        __syncthreads();

        const uint32_t sA = sb + (i & 1) * STAGE_BYTES + A_OFF;
        const uint32_t sB = sb + (i & 1) * STAGE_BYTES + B_OFF;

        #pragma unroll
        for (int mt = 0; mt < 4; mt++) {
            int r = wm * 64 + mt * 16 + a_r;
            ldmat_x4(tile_addr(sA, r, a_c),
                     ah[0][mt][0], ah[0][mt][1], ah[0][mt][2], ah[0][mt][3]);
        }
        #pragma unroll
        for (int np = 0; np < 4; np++) {
            int r = wn * 64 + np * 16 + b_r;
            uint32_t t0, t1, t2, t3;
            ldmat_x4(tile_addr(sB, r, b_c), t0, t1, t2, t3);
            bh[0][2*np][0] = t0; bh[0][2*np][1] = t1;
            bh[0][2*np+1][0] = t2; bh[0][2*np+1][1] = t3;
        }

        #pragma unroll
        for (int ks = 0; ks < 8; ks++) {
            const int cur = ks & 1;
            const int nxt = cur ^ 1;
            if (ks < 7) {
                const int kn = ks + 1;
                const uint32_t sAs = sA + (kn >> 2) * 16384;
                const uint32_t sBs = sB + (kn >> 2) * 32768;
                const int kb = (kn & 3) * 32;
                #pragma unroll
                for (int mt = 0; mt < 4; mt++) {
                    int r = wm * 64 + mt * 16 + a_r;
                    ldmat_x4(tile_addr(sAs, r, kb + a_c),
                             ah[nxt][mt][0], ah[nxt][mt][1],
                             ah[nxt][mt][2], ah[nxt][mt][3]);
                }
                #pragma unroll
                for (int np = 0; np < 4; np++) {
                    int r = wn * 64 + np * 16 + b_r;
                    uint32_t t0, t1, t2, t3;
                    ldmat_x4(tile_addr(sBs, r, kb + b_c), t0, t1, t2, t3);
                    bh[nxt][2*np][0] = t0; bh[nxt][2*np][1] = t1;
                    bh[nxt][2*np+1][0] = t2; bh[nxt][2*np+1][1] = t3;
                }
            }
            #pragma unroll
            for (int mt = 0; mt < 4; mt++)
                #pragma unroll
                for (int nj = 0; nj < 8; nj++)
                    mma_f16(acc[mt][nj],
                            ah[cur][mt][0], ah[cur][mt][1],
                            ah[cur][mt][2], ah[cur][mt][3],
                            bh[cur][nj][0], bh[cur][nj][1]);
        }
        __syncthreads();
    }

    // epilogue
    #pragma unroll
    for (int mt = 0; mt < 4; mt++) {
        #pragma unroll
        for (int nj = 0; nj < 8; nj++) {
            int m = row0 + wm * 64 + mt * 16 + (lane >> 2);
            int n = col0 + wn * 64 + nj * 8 + (lane & 3) * 2;   // even
            #pragma unroll
            for (int half = 0; half < 2; half++) {
                int mm = m + half * 8;
                float v0 = acc[mt][nj][half * 2 + 0];
                float v1 = acc[mt][nj][half * 2 + 1];
                if (MODE == 1) {
                    out[(size_t)mm * DMODEL + n]     = v0;
                    out[(size_t)mm * DMODEL + n + 1] = v1;
                } else {
                    if (n < DINNER) {
                        *(__half2*)&g_z[(size_t)mm * DINNER + n] =
                            __floats2half2_rn(v0, v1);
                    } else if (n < DINNER + CONVDIM) {
                        *(__half2*)&g_xBC[(size_t)mm * CONVDIM + (n - DINNER)] =
                            __floats2half2_rn(v0, v1);
                    } else if (n < DPROJ) {
                        int h = n - (DINNER + CONVDIM);
                        g_dt[(size_t)mm * NHEADS + h] =
                            softplus_f(v0 + dt_bias[h]);
                        g_dt[(size_t)mm * NHEADS + h + 1] =
                            softplus_f(v1 + dt_bias[h + 1]);
                    }
                }
            }
        }
    }
}

// ============================================================================
// converts
// ============================================================================
__global__ void cvt_half4(const float4* __restrict__ src,
                          __half2* __restrict__ dst, int n4)
{
    int i = blockIdx.x * blockDim.x + threadIdx.x;
    if (i >= n4) return;
    float4 v = src[i];
    dst[2 * i + 0] = __floats2half2_rn(v.x, v.y);
    dst[2 * i + 1] = __floats2half2_rn(v.z, v.w);
}

__global__ void cvt_w1_pad(const float* __restrict__ W)
{
    int i = blockIdx.x * blockDim.x + threadIdx.x;   // over NPAD1*DMODEL
    if (i >= NPAD1 * DMODEL) return;
    int r = i / DMODEL;
    float x = (r < DPROJ) ? W[(size_t)r * DMODEL + (i - r * DMODEL)] : 0.f;
    g_W1h[i] = __float2half(x);
}

// ============================================================================
// Causal depthwise conv + SiLU + split — sliding window, half2 (2 ch/thread).
// grid (BATCH*32 row-tiles, 4 ch-blocks), 260 threads -> 1040 ch-pairs.
// ============================================================================
__global__ void conv_silu_kernel(const float* __restrict__ conv_w,
                                 const float* __restrict__ conv_b)
{
    const int ch2 = blockIdx.y * 260 + threadIdx.x;   // 0..1039
    const int ch = ch2 * 2;
    const int bt = blockIdx.x;
    const int b = bt >> 5;
    const int tile = bt & 31;
    const int l0 = tile * 128;
    const int hh = ch >> 8;                           // head (pair never straddles)

    const float4 wa = *(const float4*)&conv_w[ch * 4];
    const float4 wb = *(const float4*)&conv_w[ch * 4 + 4];
    const float cba = conv_b[ch];
    const float cbb = conv_b[ch + 1];

    const __half2* xp = (const __half2*)g_xBC;        // row stride 1040
    const size_t rbase = (size_t)(b * SEQ) * 1040 + ch2;

    float2 xm3 = {0.f, 0.f}, xm2 = {0.f, 0.f}, xm1 = {0.f, 0.f};
    if (l0 > 0) {
        xm3 = __half22float2(xp[rbase + (size_t)(l0 - 3) * 1040]);
        xm2 = __half22float2(xp[rbase + (size_t)(l0 - 2) * 1040]);
        xm1 = __half22float2(xp[rbase + (size_t)(l0 - 1) * 1040]);
    }

    for (int r = 0; r < 128; r += 4) {
        const int l = l0 + r;
        float2 x0 = __half22float2(xp[rbase + (size_t)(l + 0) * 1040]);
        float2 x1 = __half22float2(xp[rbase + (size_t)(l + 1) * 1040]);
        float2 x2 = __half22float2(xp[rbase + (size_t)(l + 2) * 1040]);
        float2 x3 = __half22float2(xp[rbase + (size_t)(l + 3) * 1040]);

        float va[4], vb[4];
        va[0] = silu_f(cba + wa.x * xm3.x + wa.y * xm2.x + wa.z * xm1.x + wa.w * x0.x);
        va[1] = silu_f(cba + wa.x * xm2.x + wa.y * xm1.x + wa.z * x0.x  + wa.w * x1.x);
        va[2] = silu_f(cba + wa.x * xm1.x + wa.y * x0.x  + wa.z * x1.x  + wa.w * x2.x);
        va[3] = silu_f(cba + wa.x * x0.x  + wa.y * x1.x  + wa.z * x2.x  + wa.w * x3.x);
        vb[0] = silu_f(cbb + wb.x * xm3.y + wb.y * xm2.y + wb.z * xm1.y + wb.w * x0.y);
        vb[1] = silu_f(cbb + wb.x * xm2.y + wb.y * xm1.y + wb.z * x0.y  + wb.w * x1.y);
        vb[2] = silu_f(cbb + wb.x * xm1.y + wb.y * x0.y  + wb.z * x1.y  + wb.w * x2.y);
        vb[3] = silu_f(cbb + wb.x * x0.y  + wb.y * x1.y  + wb.z * x2.y  + wb.w * x3.y);

        #pragma unroll
        for (int q = 0; q < 4; q++) {
            const int row = b * SEQ + l + q;
            if (ch < DINNER) {
                float dtv = g_dt[(size_t)row * NHEADS + hh];
                *(__half2*)&g_xh[(size_t)row * DINNER + ch] =
                    __floats2half2_rn(va[q] * dtv, vb[q] * dtv);
            } else if (ch < DINNER + DSTATE) {
                g_Bm[(size_t)row * DSTATE + (ch - DINNER)]     = va[q];
                g_Bm[(size_t)row * DSTATE + (ch - DINNER) + 1] = vb[q];
            } else {
                g_Cm[(size_t)row * DSTATE + (ch - DINNER - DSTATE)]     = va[q];
                g_Cm[(size_t)row * DSTATE + (ch - DINNER - DSTATE) + 1] = vb[q];
            }
        }
        xm3 = x1; xm2 = x2; xm1 = x3;
    }
}

// ============================================================================
// Per-chunk states
// ============================================================================
__global__ void chunk_states_kernel(const float* __restrict__ log_A)
{
    const int id = blockIdx.x;
    const int b = id >> 9;
    const int rem = id & 511;
    const int c = rem >> 3;
    const int h = rem & 7;
    const float a = -expf(log_A[h]);

    __shared__ float Bs[CHUNKL][DSTATE];
    const int t = threadIdx.x;
    for (int i = t; i < CHUNKL * DSTATE; i += 256)
        Bs[i >> 4][i & 15] =
            g_Bm[(size_t)(b * SEQ + c * CHUNKL + (i >> 4)) * DSTATE + (i & 15)];
    __syncthreads();

    float acc[DSTATE];
    #pragma unroll
    for (int n = 0; n < DSTATE; n++) acc[n] = 0.f;

    const int p = t;
    for (int s = 0; s < CHUNKL; s++) {
        float xv = __half2float(
            g_xh[(size_t)(b * SEQ + c * CHUNKL + s) * DINNER + h * HEADDIM + p]);
        float w = expf(a * (float)(CHUNKL - 1 - s)) * xv;
        #pragma unroll
        for (int n = 0; n < DSTATE; n++) acc[n] += Bs[s][n] * w;
    }
    size_t base = ((size_t)id * HEADDIM + p) * DSTATE;
    #pragma unroll
    for (int n = 0; n < DSTATE; n++) g_states[base + n] = acc[n];
}

// ============================================================================
// Inter-chunk scan
// ============================================================================
__global__ void state_scan_kernel(const float* __restrict__ log_A)
{
    const int gid = blockIdx.x * blockDim.x + threadIdx.x;
    const int b = gid >> 15;
    const int r = gid & 32767;
    const int h = r >> 12;
    const float a = -expf(log_A[h]);
    const float d = expf(a * (float)CHUNKL);
    float P = 0.f;
    for (int c = 0; c < NCHUNK; c++) {
        size_t off = (size_t)(b * NCHUNK + c) * 32768 + r;
        g_Pst[off] = P;
        P = d * P + g_states[off];
    }
}

// ============================================================================
// SSD Y kernel — float4 G rows + 4-row tt blocking; fp16 xh in / Y out
// ============================================================================
__global__ void ssd_y_kernel(const float* __restrict__ log_A,
                             const float* __restrict__ D_skip)
{
    extern __shared__ float sh[];
    float* Bs = sh;                   // 64*16
    float* Cs = sh + 1024;            // 64*16
    float* G  = sh + 2048;            // 64*64
    float* xs = sh + 6144;            // 64*256

    const int id = blockIdx.x;
    const int b = id >> 9;
    const int rem = id & 511;
    const int c = rem >> 3;
    const int h = rem & 7;
    const float a = -expf(log_A[h]);
    const int t = threadIdx.x;
    const int rowbase = b * SEQ + c * CHUNKL;

    for (int i = t; i < CHUNKL * DSTATE; i += 256) {
        size_t gi = (size_t)(rowbase + (i >> 4)) * DSTATE + (i & 15);
        Bs[i] = g_Bm[gi];
        Cs[i] = g_Cm[gi];
    }
    for (int i = t; i < CHUNKL * HEADDIM; i += 256) {
        int s = i >> 8, p = i & 255;
        xs[i] = __half2float(
            g_xh[(size_t)(rowbase + s) * DINNER + h * HEADDIM + p]);
    }
    __syncthreads();

    for (int e = t * 16; e < t * 16 + 16; e++) {
        int tt = e >> 6, ss = e & 63;
        float val = 0.f;
        if (ss <= tt) {
            float dot = 0.f;
            #pragma unroll
            for (int n = 0; n < DSTATE; n++) dot += Cs[tt * 16 + n] * Bs[ss * 16 + n];
            val = expf(a * (float)(tt - ss)) * dot;
        }
        G[e] = val;
    }
    __syncthreads();

    const int p = t;
    float Preg[DSTATE];
    size_t pbase = ((size_t)id * HEADDIM + p) * DSTATE;
    #pragma unroll
    for (int n = 0; n < DSTATE; n++) Preg[n] = g_Pst[pbase + n];
    const float dsk = D_skip[h];

    for (int tt0 = 0; tt0 < CHUNKL; tt0 += 4) {
        float aq[4] = {0.f, 0.f, 0.f, 0.f};
        const int smax = tt0 + 4;
        for (int ss = 0; ss < smax; ss += 4) {
            float xv0 = xs[(ss + 0) * 256 + p];
            float xv1 = xs[(ss + 1) * 256 + p];
            float xv2 = xs[(ss + 2) * 256 + p];
            float xv3 = xs[(ss + 3) * 256 + p];
            #pragma unroll
            for (int q = 0; q < 4; q++) {
                float4 g4 = *(const float4*)&G[(tt0 + q) * 64 + ss];
                aq[q] += g4.x * xv0 + g4.y * xv1 + g4.z * xv2 + g4.w * xv3;
            }
        }
        #pragma unroll
        for (int q = 0; q < 4; q++) {
            const int tt = tt0 + q;
            float offv = 0.f;
            const float4* c4 = (const float4*)&Cs[tt * 16];
            #pragma unroll
            for (int n4 = 0; n4 < 4; n4++) {
                float4 cv = c4[n4];
                offv += cv.x * Preg[n4 * 4 + 0] + cv.y * Preg[n4 * 4 + 1] +
                        cv.z * Preg[n4 * 4 + 2] + cv.w * Preg[n4 * 4 + 3];
            }
            float y = aq[q] + expf(a * (float)(tt + 1)) * offv +
                      dsk * xs[tt * 256 + p];
            g_Y[(size_t)(rowbase + tt) * DINNER + h * HEADDIM + p] =
                __float2half(y);
        }
    }
}

// ============================================================================
// Gate + RMS norm; fp16 in (Y, z), fp16 out (Yh)
// ============================================================================
__global__ void rms_gate_kernel(const float* __restrict__ norm_w)
{
    const int row = blockIdx.x;
    const int t = threadIdx.x;
    float v[8];
    float ss = 0.f;
    #pragma unroll
    for (int k = 0; k < 8; k++) {
        int ch = k * 256 + t;
        float Yv = __half2float(g_Y[(size_t)row * DINNER + ch]);
        float zv = __half2float(g_z[(size_t)row * DINNER + ch]);
        float val = Yv * silu_f(zv);
        v[k] = val;
        ss += val * val;
    }
    __shared__ float red[256];
    red[t] = ss;
    __syncthreads();
    for (int st = 128; st > 0; st >>= 1) {
        if (t < st) red[t] += red[t + st];
        __syncthreads();
    }
    float inv = rsqrtf(red[0] / (float)DINNER + 1e-5f);
    #pragma unroll
    for (int k = 0; k < 8; k++) {
        int ch = k * 256 + t;
        g_Yh[(size_t)row * DINNER + ch] = __float2half(v[k] * inv * norm_w[ch]);
    }
}

// ============================================================================
// Launch
// ============================================================================
extern "C" void kernel_launch(void* const* d_in, const int* in_sizes, int n_in,
                              void* d_out, int out_size)
{
    const float* input   = (const float*)d_in[0];
    const float* W_in    = (const float*)d_in[1];
    const float* conv_w  = (const float*)d_in[2];
    const float* conv_b  = (const float*)d_in[3];
    const float* dt_bias = (const float*)d_in[4];
    const float* log_A   = (const float*)d_in[5];
    const float* D_skip  = (const float*)d_in[6];
    const float* norm_w  = (const float*)d_in[7];
    const float* W_out   = (const float*)d_in[8];
    float* out = (float*)d_out;

    (void)in_sizes; (void)n_in; (void)out_size;

    const int GSMEM = 2 * STAGE_BYTES;               // 196608 B
    const int SMEM_Y = (1024 + 1024 + 4096 + 16384) * 4;
    cudaFuncSetAttribute(mma_gemm<0>, cudaFuncAttributeMaxDynamicSharedMemorySize, GSMEM);
    cudaFuncSetAttribute(mma_gemm<1>, cudaFuncAttributeMaxDynamicSharedMemorySize, GSMEM);
    cudaFuncSetAttribute(ssd_y_kernel, cudaFuncAttributeMaxDynamicSharedMemorySize, SMEM_Y);

    __half *Xh, *W2h, *Yh, *W1h;
    cudaGetSymbolAddress((void**)&Xh,  g_Xh);
    cudaGetSymbolAddress((void**)&W2h, g_W2h);
    cudaGetSymbolAddress((void**)&Yh,  g_Yh);
    cudaGetSymbolAddress((void**)&W1h, g_W1h);

    // converts (vectorized)
    {
        int n4 = NROWS * DMODEL / 4;
        cvt_half4<<<(n4 + 255) / 256, 256>>>((const float4*)input,
                                             (__half2*)Xh, n4);
    }
    cvt_w1_pad<<<(NPAD1 * DMODEL + 255) / 256, 256>>>(W_in);
    {
        int n4 = DMODEL * DINNER / 4;
        cvt_half4<<<(n4 + 255) / 256, 256>>>((const float4*)W_out,
                                             (__half2*)W2h, n4);
    }

    // 1) in-projection
    mma_gemm<0><<<dim3(NPAD1 / 256, NROWS / 128), 256, GSMEM>>>(
        Xh, W1h, DMODEL, nullptr, dt_bias);

    // 2) conv + silu + split (half2 sliding window)
    conv_silu_kernel<<<dim3(BATCH * 32, 4), 260>>>(conv_w, conv_b);

    // 3) per-chunk states
    chunk_states_kernel<<<BATCH * NCHUNK * NHEADS, 256>>>(log_A);

    // 4) inter-chunk scan
    state_scan_kernel<<<(BATCH * NHEADS * HEADDIM * DSTATE) / 256, 256>>>(log_A);

    // 5) Y
    ssd_y_kernel<<<BATCH * NCHUNK * NHEADS, 256, SMEM_Y>>>(log_A, D_skip);

    // 6) gate + RMS norm
    rms_gate_kernel<<<NROWS, 256>>>(norm_w);

    // 7) out-projection
    mma_gemm<1><<<dim3(DMODEL / 256, NROWS / 128), 256, GSMEM>>>(
        Yh, W2h, DINNER, out, nullptr);
}

// round 16
// speedup vs baseline: 2.2869x; 1.0878x over previous
#include <cuda_runtime.h>
#include <cuda_fp16.h>
#include <math.h>
#include <stdint.h>

// ---------------- problem constants ----------------
#define BATCH   4
#define SEQ     4096
#define DMODEL  1024
#define DSTATE  16
#define DCONV   4
#define NHEADS  8
#define CHUNKL  64
#define DINNER  2048
#define HEADDIM 256
#define CONVDIM 2080              // DINNER + 2*DSTATE
#define DPROJ   4136              // 2*DINNER + 2*DSTATE + NHEADS
#define NROWS   (BATCH*SEQ)       // 16384
#define NCHUNK  (SEQ/CHUNKL)      // 64
#define NPAD1   4352              // 34*128 padded N for GEMM1

// ---------------- scratch (static device globals) ----------------
__device__ __half g_z    [NROWS*(size_t)DINNER];
__device__ __half g_xBC  [NROWS*(size_t)CONVDIM];
__device__ float  g_dt   [NROWS*(size_t)NHEADS];
__device__ __half g_xh   [NROWS*(size_t)DINNER];
__device__ float  g_Bm   [NROWS*(size_t)DSTATE];
__device__ float  g_Cm   [NROWS*(size_t)DSTATE];
__device__ float  g_states[(size_t)BATCH*NCHUNK*NHEADS*HEADDIM*DSTATE];
__device__ float  g_Pst  [(size_t)BATCH*NCHUNK*NHEADS*HEADDIM*DSTATE];
__device__ __half g_Y    [NROWS*(size_t)DINNER];

// fp16 operand buffers
__device__ __half g_Xh [NROWS*(size_t)DMODEL];
__device__ __half g_W1h[(size_t)NPAD1*DMODEL];
__device__ __half g_W2h[(size_t)DMODEL*DINNER];
__device__ __half g_Yh [NROWS*(size_t)DINNER];

__device__ __forceinline__ float softplus_f(float x) {
    return (x > 20.f) ? x : log1pf(expf(x));
}
__device__ __forceinline__ float silu_f(float x) {
    return x / (1.f + expf(-x));
}

__device__ __forceinline__ uint32_t smem_u32(const void* p) {
    uint32_t a;
    asm("{ .reg .u64 t; cvta.to.shared.u64 t, %1; cvt.u32.u64 %0, t; }"
        : "=r"(a) : "l"(p));
    return a;
}

#define CP_COMMIT() asm volatile("cp.async.commit_group;" ::: "memory")
#define CP_WAIT_N(n) asm volatile("cp.async.wait_group %0;" :: "n"(n) : "memory")

__device__ __forceinline__ void ldmat_x4(uint32_t a, uint32_t& r0, uint32_t& r1,
                                         uint32_t& r2, uint32_t& r3) {
    asm volatile("ldmatrix.sync.aligned.m8n8.x4.shared.b16 {%0,%1,%2,%3}, [%4];"
                 : "=r"(r0), "=r"(r1), "=r"(r2), "=r"(r3) : "r"(a));
}
__device__ __forceinline__ void mma_f16(float* c, uint32_t a0, uint32_t a1,
                                        uint32_t a2, uint32_t a3,
                                        uint32_t b0, uint32_t b1) {
    asm volatile(
        "mma.sync.aligned.m16n8k16.row.col.f32.f16.f16.f32 "
        "{%0,%1,%2,%3}, {%4,%5,%6,%7}, {%8,%9}, {%0,%1,%2,%3};"
        : "+f"(c[0]), "+f"(c[1]), "+f"(c[2]), "+f"(c[3])
        : "r"(a0), "r"(a1), "r"(a2), "r"(a3), "r"(b0), "r"(b1));
}

// copy a 128x64-fp16 tile (128B rows, SW128 swizzle) global->smem via cp.async
__device__ __forceinline__ void load_tile(uint32_t sbase, const __half* g,
                                          int rowbase, int K, int k0, int tid) {
    #pragma unroll
    for (int it = 0; it < 4; it++) {
        int chunk = tid + it * 256;          // 0..1023 : 16B units
        int row = chunk >> 3;
        int c16 = chunk & 7;
        uint32_t soff = (uint32_t)(row * 128 + c16 * 16);
        soff ^= ((soff >> 3) & 0x70);        // SW128
        const void* gp = g + (size_t)(rowbase + row) * K + k0 + c16 * 8;
        asm volatile("cp.async.cg.shared.global [%0], [%1], 16;"
                     :: "r"(sbase + soff), "l"(gp) : "memory");
    }
}

__device__ __forceinline__ uint32_t tile_addr(uint32_t base, int row, int colb) {
    uint32_t off = (uint32_t)(row * 128 + colb);
    off ^= ((off >> 3) & 0x70);
    return base + off;
}

// ============================================================================
// mma.sync fp16 GEMM (NT): CTA tile 128x128, K-chunk 64, 2-stage double
// buffer, 256 threads (8 warps 2x4, warp tile 64x32), 2 CTAs/SM.
// MODE 0: in-proj epilogue (half2 z/xBC, f32 dt); MODE 1: f32 store.
// ============================================================================
#define STAGE_BYTES 32768        // A 16KB + B 16KB
#define A_OFF       0
#define B_OFF       16384

template<int MODE>
__global__ __launch_bounds__(256, 2)
void mma_gemm(const __half* __restrict__ A, const __half* __restrict__ B,
              int K, float* __restrict__ out, const float* __restrict__ dt_bias)
{
    extern __shared__ char smem[];
    const uint32_t sb = smem_u32(smem);
    const int tid = threadIdx.x;
    const int wid = tid >> 5;
    const int lane = tid & 31;
    const int row0 = blockIdx.y * 128;
    const int col0 = blockIdx.x * 128;
    const int NC = K / 64;

    const int wm = wid >> 2;          // 0..1 : warp row (64 rows)
    const int wn = wid & 3;           // 0..3 : warp col (32 cols)

    float acc[4][4][4];               // 64 regs
    #pragma unroll
    for (int i = 0; i < 4; i++)
        #pragma unroll
        for (int j = 0; j < 4; j++)
            #pragma unroll
            for (int r = 0; r < 4; r++) acc[i][j][r] = 0.f;

    const int grp = lane >> 3;
    const int wit = lane & 7;
    const int a_r = wit + (grp & 1) * 8;
    const int a_c = (grp >> 1) * 16;
    const int b_r = wit + (grp >> 1) * 8;
    const int b_c = (grp & 1) * 16;

    // prologue: chunk 0 -> stage 0
    load_tile(sb + A_OFF, A, row0, K, 0, tid);
    load_tile(sb + B_OFF, B, col0, K, 0, tid);
    CP_COMMIT();

    for (int i = 0; i < NC; i++) {
        if (i + 1 < NC) {
            uint32_t stb = sb + ((i + 1) & 1) * STAGE_BYTES;
            load_tile(stb + A_OFF, A, row0, K, (i + 1) * 64, tid);
            load_tile(stb + B_OFF, B, col0, K, (i + 1) * 64, tid);
            CP_COMMIT();
            CP_WAIT_N(1);
        } else {
            CP_WAIT_N(0);
        }
        __syncthreads();

        const uint32_t sA = sb + (i & 1) * STAGE_BYTES + A_OFF;
        const uint32_t sB = sb + (i & 1) * STAGE_BYTES + B_OFF;

        #pragma unroll
        for (int ks = 0; ks < 4; ks++) {
            const int kb = ks * 32;

            uint32_t ah[4][4];
            #pragma unroll
            for (int mt = 0; mt < 4; mt++) {
                int r = wm * 64 + mt * 16 + a_r;
                ldmat_x4(tile_addr(sA, r, kb + a_c),
                         ah[mt][0], ah[mt][1], ah[mt][2], ah[mt][3]);
            }
            uint32_t bh[4][2];
            #pragma unroll
            for (int np = 0; np < 2; np++) {
                int r = wn * 32 + np * 16 + b_r;
                uint32_t t0, t1, t2, t3;
                ldmat_x4(tile_addr(sB, r, kb + b_c), t0, t1, t2, t3);
                bh[2*np][0] = t0; bh[2*np][1] = t1;
                bh[2*np+1][0] = t2; bh[2*np+1][1] = t3;
            }

            #pragma unroll
            for (int mt = 0; mt < 4; mt++)
                #pragma unroll
                for (int nj = 0; nj < 4; nj++)
                    mma_f16(acc[mt][nj], ah[mt][0], ah[mt][1], ah[mt][2], ah[mt][3],
                            bh[nj][0], bh[nj][1]);
        }
        __syncthreads();
    }

    // epilogue
    #pragma unroll
    for (int mt = 0; mt < 4; mt++) {
        #pragma unroll
        for (int nj = 0; nj < 4; nj++) {
            int m = row0 + wm * 64 + mt * 16 + (lane >> 2);
            int n = col0 + wn * 32 + nj * 8 + (lane & 3) * 2;   // even
            #pragma unroll
            for (int half = 0; half < 2; half++) {
                int mm = m + half * 8;
                float v0 = acc[mt][nj][half * 2 + 0];
                float v1 = acc[mt][nj][half * 2 + 1];
                if (MODE == 1) {
                    out[(size_t)mm * DMODEL + n]     = v0;
                    out[(size_t)mm * DMODEL + n + 1] = v1;
                } else {
                    if (n < DINNER) {
                        *(__half2*)&g_z[(size_t)mm * DINNER + n] =
                            __floats2half2_rn(v0, v1);
                    } else if (n < DINNER + CONVDIM) {
                        *(__half2*)&g_xBC[(size_t)mm * CONVDIM + (n - DINNER)] =
                            __floats2half2_rn(v0, v1);
                    } else if (n < DPROJ) {
                        int h = n - (DINNER + CONVDIM);
                        g_dt[(size_t)mm * NHEADS + h] =
                            softplus_f(v0 + dt_bias[h]);
                        g_dt[(size_t)mm * NHEADS + h + 1] =
                            softplus_f(v1 + dt_bias[h + 1]);
                    }
                }
            }
        }
    }
}

// ============================================================================
// converts
// ============================================================================
__global__ void cvt_half4(const float4* __restrict__ src,
                          __half2* __restrict__ dst, int n4)
{
    int i = blockIdx.x * blockDim.x + threadIdx.x;
    if (i >= n4) return;
    float4 v = src[i];
    dst[2 * i + 0] = __floats2half2_rn(v.x, v.y);
    dst[2 * i + 1] = __floats2half2_rn(v.z, v.w);
}

__global__ void cvt_w1_pad(const float* __restrict__ W)
{
    int i = blockIdx.x * blockDim.x + threadIdx.x;   // over NPAD1*DMODEL
    if (i >= NPAD1 * DMODEL) return;
    int r = i / DMODEL;
    float x = (r < DPROJ) ? W[(size_t)r * DMODEL + (i - r * DMODEL)] : 0.f;
    g_W1h[i] = __float2half(x);
}

// ============================================================================
// Causal depthwise conv + SiLU + split — sliding window, half2 (2 ch/thread).
// ============================================================================
__global__ void conv_silu_kernel(const float* __restrict__ conv_w,
                                 const float* __restrict__ conv_b)
{
    const int ch2 = blockIdx.y * 260 + threadIdx.x;   // 0..1039
    const int ch = ch2 * 2;
    const int bt = blockIdx.x;
    const int b = bt >> 5;
    const int tile = bt & 31;
    const int l0 = tile * 128;
    const int hh = ch >> 8;

    const float4 wa = *(const float4*)&conv_w[ch * 4];
    const float4 wb = *(const float4*)&conv_w[ch * 4 + 4];
    const float cba = conv_b[ch];
    const float cbb = conv_b[ch + 1];

    const __half2* xp = (const __half2*)g_xBC;        // row stride 1040
    const size_t rbase = (size_t)(b * SEQ) * 1040 + ch2;

    float2 xm3 = {0.f, 0.f}, xm2 = {0.f, 0.f}, xm1 = {0.f, 0.f};
    if (l0 > 0) {
        xm3 = __half22float2(xp[rbase + (size_t)(l0 - 3) * 1040]);
        xm2 = __half22float2(xp[rbase + (size_t)(l0 - 2) * 1040]);
        xm1 = __half22float2(xp[rbase + (size_t)(l0 - 1) * 1040]);
    }

    for (int r = 0; r < 128; r += 4) {
        const int l = l0 + r;
        float2 x0 = __half22float2(xp[rbase + (size_t)(l + 0) * 1040]);
        float2 x1 = __half22float2(xp[rbase + (size_t)(l + 1) * 1040]);
        float2 x2 = __half22float2(xp[rbase + (size_t)(l + 2) * 1040]);
        float2 x3 = __half22float2(xp[rbase + (size_t)(l + 3) * 1040]);

        float va[4], vb[4];
        va[0] = silu_f(cba + wa.x * xm3.x + wa.y * xm2.x + wa.z * xm1.x + wa.w * x0.x);
        va[1] = silu_f(cba + wa.x * xm2.x + wa.y * xm1.x + wa.z * x0.x  + wa.w * x1.x);
        va[2] = silu_f(cba + wa.x * xm1.x + wa.y * x0.x  + wa.z * x1.x  + wa.w * x2.x);
        va[3] = silu_f(cba + wa.x * x0.x  + wa.y * x1.x  + wa.z * x2.x  + wa.w * x3.x);
        vb[0] = silu_f(cbb + wb.x * xm3.y + wb.y * xm2.y + wb.z * xm1.y + wb.w * x0.y);
        vb[1] = silu_f(cbb + wb.x * xm2.y + wb.y * xm1.y + wb.z * x0.y  + wb.w * x1.y);
        vb[2] = silu_f(cbb + wb.x * xm1.y + wb.y * x0.y  + wb.z * x1.y  + wb.w * x2.y);
        vb[3] = silu_f(cbb + wb.x * x0.y  + wb.y * x1.y  + wb.z * x2.y  + wb.w * x3.y);

        #pragma unroll
        for (int q = 0; q < 4; q++) {
            const int row = b * SEQ + l + q;
            if (ch < DINNER) {
                float dtv = g_dt[(size_t)row * NHEADS + hh];
                *(__half2*)&g_xh[(size_t)row * DINNER + ch] =
                    __floats2half2_rn(va[q] * dtv, vb[q] * dtv);
            } else if (ch < DINNER + DSTATE) {
                g_Bm[(size_t)row * DSTATE + (ch - DINNER)]     = va[q];
                g_Bm[(size_t)row * DSTATE + (ch - DINNER) + 1] = vb[q];
            } else {
                g_Cm[(size_t)row * DSTATE + (ch - DINNER - DSTATE)]     = va[q];
                g_Cm[(size_t)row * DSTATE + (ch - DINNER - DSTATE) + 1] = vb[q];
            }
        }
        xm3 = x1; xm2 = x2; xm1 = x3;
    }
}

// ============================================================================
// Per-chunk states
// ============================================================================
__global__ void chunk_states_kernel(const float* __restrict__ log_A)
{
    const int id = blockIdx.x;
    const int b = id >> 9;
    const int rem = id & 511;
    const int c = rem >> 3;
    const int h = rem & 7;
    const float a = -expf(log_A[h]);

    __shared__ float Bs[CHUNKL][DSTATE];
    const int t = threadIdx.x;
    for (int i = t; i < CHUNKL * DSTATE; i += 256)
        Bs[i >> 4][i & 15] =
            g_Bm[(size_t)(b * SEQ + c * CHUNKL + (i >> 4)) * DSTATE + (i & 15)];
    __syncthreads();

    float acc[DSTATE];
    #pragma unroll
    for (int n = 0; n < DSTATE; n++) acc[n] = 0.f;

    const int p = t;
    for (int s = 0; s < CHUNKL; s++) {
        float xv = __half2float(
            g_xh[(size_t)(b * SEQ + c * CHUNKL + s) * DINNER + h * HEADDIM + p]);
        float w = expf(a * (float)(CHUNKL - 1 - s)) * xv;
        #pragma unroll
        for (int n = 0; n < DSTATE; n++) acc[n] += Bs[s][n] * w;
    }
    size_t base = ((size_t)id * HEADDIM + p) * DSTATE;
    #pragma unroll
    for (int n = 0; n < DSTATE; n++) g_states[base + n] = acc[n];
}

// ============================================================================
// Inter-chunk scan
// ============================================================================
__global__ void state_scan_kernel(const float* __restrict__ log_A)
{
    const int gid = blockIdx.x * blockDim.x + threadIdx.x;
    const int b = gid >> 15;
    const int r = gid & 32767;
    const int h = r >> 12;
    const float a = -expf(log_A[h]);
    const float d = expf(a * (float)CHUNKL);
    float P = 0.f;
    for (int c = 0; c < NCHUNK; c++) {
        size_t off = (size_t)(b * NCHUNK + c) * 32768 + r;
        g_Pst[off] = P;
        P = d * P + g_states[off];
    }
}

// ============================================================================
// SSD Y kernel — float4 G rows + 4-row tt blocking; fp16 xh in / Y out
// ============================================================================
__global__ void ssd_y_kernel(const float* __restrict__ log_A,
                             const float* __restrict__ D_skip)
{
    extern __shared__ float sh[];
    float* Bs = sh;                   // 64*16
    float* Cs = sh + 1024;            // 64*16
    float* G  = sh + 2048;            // 64*64
    float* xs = sh + 6144;            // 64*256

    const int id = blockIdx.x;
    const int b = id >> 9;
    const int rem = id & 511;
    const int c = rem >> 3;
    const int h = rem & 7;
    const float a = -expf(log_A[h]);
    const int t = threadIdx.x;
    const int rowbase = b * SEQ + c * CHUNKL;

    for (int i = t; i < CHUNKL * DSTATE; i += 256) {
        size_t gi = (size_t)(rowbase + (i >> 4)) * DSTATE + (i & 15);
        Bs[i] = g_Bm[gi];
        Cs[i] = g_Cm[gi];
    }
    for (int i = t; i < CHUNKL * HEADDIM; i += 256) {
        int s = i >> 8, p = i & 255;
        xs[i] = __half2float(
            g_xh[(size_t)(rowbase + s) * DINNER + h * HEADDIM + p]);
    }
    __syncthreads();

    for (int e = t * 16; e < t * 16 + 16; e++) {
        int tt = e >> 6, ss = e & 63;
        float val = 0.f;
        if (ss <= tt) {
            float dot = 0.f;
            #pragma unroll
            for (int n = 0; n < DSTATE; n++) dot += Cs[tt * 16 + n] * Bs[ss * 16 + n];
            val = expf(a * (float)(tt - ss)) * dot;
        }
        G[e] = val;
    }
    __syncthreads();

    const int p = t;
    float Preg[DSTATE];
    size_t pbase = ((size_t)id * HEADDIM + p) * DSTATE;
    #pragma unroll
    for (int n = 0; n < DSTATE; n++) Preg[n] = g_Pst[pbase + n];
    const float dsk = D_skip[h];

    for (int tt0 = 0; tt0 < CHUNKL; tt0 += 4) {
        float aq[4] = {0.f, 0.f, 0.f, 0.f};
        const int smax = tt0 + 4;
        for (int ss = 0; ss < smax; ss += 4) {
            float xv0 = xs[(ss + 0) * 256 + p];
            float xv1 = xs[(ss + 1) * 256 + p];
            float xv2 = xs[(ss + 2) * 256 + p];
            float xv3 = xs[(ss + 3) * 256 + p];
            #pragma unroll
            for (int q = 0; q < 4; q++) {
                float4 g4 = *(const float4*)&G[(tt0 + q) * 64 + ss];
                aq[q] += g4.x * xv0 + g4.y * xv1 + g4.z * xv2 + g4.w * xv3;
            }
        }
        #pragma unroll
        for (int q = 0; q < 4; q++) {
            const int tt = tt0 + q;
            float offv = 0.f;
            const float4* c4 = (const float4*)&Cs[tt * 16];
            #pragma unroll
            for (int n4 = 0; n4 < 4; n4++) {
                float4 cv = c4[n4];
                offv += cv.x * Preg[n4 * 4 + 0] + cv.y * Preg[n4 * 4 + 1] +
                        cv.z * Preg[n4 * 4 + 2] + cv.w * Preg[n4 * 4 + 3];
            }
            float y = aq[q] + expf(a * (float)(tt + 1)) * offv +
                      dsk * xs[tt * 256 + p];
            g_Y[(size_t)(rowbase + tt) * DINNER + h * HEADDIM + p] =
                __float2half(y);
        }
    }
}

// ============================================================================
// Gate + RMS norm; fp16 in (Y, z), fp16 out (Yh)
// ============================================================================
__global__ void rms_gate_kernel(const float* __restrict__ norm_w)
{
    const int row = blockIdx.x;
    const int t = threadIdx.x;
    float v[8];
    float ss = 0.f;
    #pragma unroll
    for (int k = 0; k < 8; k++) {
        int ch = k * 256 + t;
        float Yv = __half2float(g_Y[(size_t)row * DINNER + ch]);
        float zv = __half2float(g_z[(size_t)row * DINNER + ch]);
        float val = Yv * silu_f(zv);
        v[k] = val;
        ss += val * val;
    }
    __shared__ float red[256];
    red[t] = ss;
    __syncthreads();
    for (int st = 128; st > 0; st >>= 1) {
        if (t < st) red[t] += red[t + st];
        __syncthreads();
    }
    float inv = rsqrtf(red[0] / (float)DINNER + 1e-5f);
    #pragma unroll
    for (int k = 0; k < 8; k++) {
        int ch = k * 256 + t;
        g_Yh[(size_t)row * DINNER + ch] = __float2half(v[k] * inv * norm_w[ch]);
    }
}

// ============================================================================
// Launch
// ============================================================================
extern "C" void kernel_launch(void* const* d_in, const int* in_sizes, int n_in,
                              void* d_out, int out_size)
{
    const float* input   = (const float*)d_in[0];
    const float* W_in    = (const float*)d_in[1];
    const float* conv_w  = (const float*)d_in[2];
    const float* conv_b  = (const float*)d_in[3];
    const float* dt_bias = (const float*)d_in[4];
    const float* log_A   = (const float*)d_in[5];
    const float* D_skip  = (const float*)d_in[6];
    const float* norm_w  = (const float*)d_in[7];
    const float* W_out   = (const float*)d_in[8];
    float* out = (float*)d_out;

    (void)in_sizes; (void)n_in; (void)out_size;

    const int GSMEM = 2 * STAGE_BYTES;               // 65536 B per CTA
    const int SMEM_Y = (1024 + 1024 + 4096 + 16384) * 4;
    cudaFuncSetAttribute(mma_gemm<0>, cudaFuncAttributeMaxDynamicSharedMemorySize, GSMEM);
    cudaFuncSetAttribute(mma_gemm<1>, cudaFuncAttributeMaxDynamicSharedMemorySize, GSMEM);
    cudaFuncSetAttribute(ssd_y_kernel, cudaFuncAttributeMaxDynamicSharedMemorySize, SMEM_Y);

    __half *Xh, *W2h, *Yh, *W1h;
    cudaGetSymbolAddress((void**)&Xh,  g_Xh);
    cudaGetSymbolAddress((void**)&W2h, g_W2h);
    cudaGetSymbolAddress((void**)&Yh,  g_Yh);
    cudaGetSymbolAddress((void**)&W1h, g_W1h);

    // converts (vectorized)
    {
        int n4 = NROWS * DMODEL / 4;
        cvt_half4<<<(n4 + 255) / 256, 256>>>((const float4*)input,
                                             (__half2*)Xh, n4);
    }
    cvt_w1_pad<<<(NPAD1 * DMODEL + 255) / 256, 256>>>(W_in);
    {
        int n4 = DMODEL * DINNER / 4;
        cvt_half4<<<(n4 + 255) / 256, 256>>>((const float4*)W_out,
                                             (__half2*)W2h, n4);
    }

    // 1) in-projection
    mma_gemm<0><<<dim3(NPAD1 / 128, NROWS / 128), 256, GSMEM>>>(
        Xh, W1h, DMODEL, nullptr, dt_bias);

    // 2) conv + silu + split (half2 sliding window)
    conv_silu_kernel<<<dim3(BATCH * 32, 4), 260>>>(conv_w, conv_b);

    // 3) per-chunk states
    chunk_states_kernel<<<BATCH * NCHUNK * NHEADS, 256>>>(log_A);

    // 4) inter-chunk scan
    state_scan_kernel<<<(BATCH * NHEADS * HEADDIM * DSTATE) / 256, 256>>>(log_A);

    // 5) Y
    ssd_y_kernel<<<BATCH * NCHUNK * NHEADS, 256, SMEM_Y>>>(log_A, D_skip);

    // 6) gate + RMS norm
    rms_gate_kernel<<<NROWS, 256>>>(norm_w);

    // 7) out-projection
    mma_gemm<1><<<dim3(DMODEL / 128, NROWS / 128), 256, GSMEM>>>(
        Yh, W2h, DINNER, out, nullptr);
}

// round 17
// speedup vs baseline: 2.3578x; 1.0310x over previous
#include <cuda_runtime.h>
#include <cuda_fp16.h>
#include <math.h>
#include <stdint.h>

// ---------------- problem constants ----------------
#define BATCH   4
#define SEQ     4096
#define DMODEL  1024
#define DSTATE  16
#define DCONV   4
#define NHEADS  8
#define CHUNKL  64
#define DINNER  2048
#define HEADDIM 256
#define CONVDIM 2080              // DINNER + 2*DSTATE
#define DPROJ   4136              // 2*DINNER + 2*DSTATE + NHEADS
#define NROWS   (BATCH*SEQ)       // 16384
#define NCHUNK  (SEQ/CHUNKL)      // 64
#define NPAD1   4352              // 34*128 padded N for GEMM1

// ---------------- scratch (static device globals) ----------------
__device__ __half g_z    [NROWS*(size_t)DINNER];
__device__ __half g_xBC  [NROWS*(size_t)CONVDIM];
__device__ float  g_dt   [NROWS*(size_t)NHEADS];
__device__ __half g_xh   [NROWS*(size_t)DINNER];
__device__ float  g_Bm   [NROWS*(size_t)DSTATE];
__device__ float  g_Cm   [NROWS*(size_t)DSTATE];
__device__ __half g_states[(size_t)BATCH*NCHUNK*NHEADS*HEADDIM*DSTATE];
__device__ __half g_Pst  [(size_t)BATCH*NCHUNK*NHEADS*HEADDIM*DSTATE];
__device__ __half g_Y    [NROWS*(size_t)DINNER];

// fp16 operand buffers
__device__ __half g_Xh [NROWS*(size_t)DMODEL];
__device__ __half g_W1h[(size_t)NPAD1*DMODEL];
__device__ __half g_W2h[(size_t)DMODEL*DINNER];
__device__ __half g_Yh [NROWS*(size_t)DINNER];

__device__ __forceinline__ float softplus_f(float x) {
    return (x > 20.f) ? x : log1pf(expf(x));
}
__device__ __forceinline__ float silu_f(float x) {
    return x / (1.f + expf(-x));
}

__device__ __forceinline__ uint32_t smem_u32(const void* p) {
    uint32_t a;
    asm("{ .reg .u64 t; cvta.to.shared.u64 t, %1; cvt.u32.u64 %0, t; }"
        : "=r"(a) : "l"(p));
    return a;
}

#define CP_COMMIT() asm volatile("cp.async.commit_group;" ::: "memory")
#define CP_WAIT_N(n) asm volatile("cp.async.wait_group %0;" :: "n"(n) : "memory")

__device__ __forceinline__ void ldmat_x4(uint32_t a, uint32_t& r0, uint32_t& r1,
                                         uint32_t& r2, uint32_t& r3) {
    asm volatile("ldmatrix.sync.aligned.m8n8.x4.shared.b16 {%0,%1,%2,%3}, [%4];"
                 : "=r"(r0), "=r"(r1), "=r"(r2), "=r"(r3) : "r"(a));
}
__device__ __forceinline__ void mma_f16(float* c, uint32_t a0, uint32_t a1,
                                        uint32_t a2, uint32_t a3,
                                        uint32_t b0, uint32_t b1) {
    asm volatile(
        "mma.sync.aligned.m16n8k16.row.col.f32.f16.f16.f32 "
        "{%0,%1,%2,%3}, {%4,%5,%6,%7}, {%8,%9}, {%0,%1,%2,%3};"
        : "+f"(c[0]), "+f"(c[1]), "+f"(c[2]), "+f"(c[3])
        : "r"(a0), "r"(a1), "r"(a2), "r"(a3), "r"(b0), "r"(b1));
}

// copy a 128x64-fp16 tile (128B rows, SW128 swizzle) global->smem via cp.async
__device__ __forceinline__ void load_tile(uint32_t sbase, const __half* g,
                                          int rowbase, int K, int k0, int tid) {
    #pragma unroll
    for (int it = 0; it < 4; it++) {
        int chunk = tid + it * 256;          // 0..1023 : 16B units
        int row = chunk >> 3;
        int c16 = chunk & 7;
        uint32_t soff = (uint32_t)(row * 128 + c16 * 16);
        soff ^= ((soff >> 3) & 0x70);        // SW128
        const void* gp = g + (size_t)(rowbase + row) * K + k0 + c16 * 8;
        asm volatile("cp.async.cg.shared.global [%0], [%1], 16;"
                     :: "r"(sbase + soff), "l"(gp) : "memory");
    }
}

__device__ __forceinline__ uint32_t tile_addr(uint32_t base, int row, int colb) {
    uint32_t off = (uint32_t)(row * 128 + colb);
    off ^= ((off >> 3) & 0x70);
    return base + off;
}

// ============================================================================
// mma.sync fp16 GEMM (NT): CTA tile 128x128, K-chunk 64, 3-stage cp.async
// pipeline, 256 threads (8 warps 2x4, warp tile 64x32), 2 CTAs/SM.
// MODE 0: in-proj epilogue (half2 z/xBC, f32 dt); MODE 1: f32 store.
// ============================================================================
#define STAGE_BYTES 32768        // A 16KB + B 16KB
#define A_OFF       0
#define B_OFF       16384

template<int MODE>
__global__ __launch_bounds__(256, 2)
void mma_gemm(const __half* __restrict__ A, const __half* __restrict__ B,
              int K, float* __restrict__ out, const float* __restrict__ dt_bias)
{
    extern __shared__ char smem[];
    const uint32_t sb = smem_u32(smem);
    const int tid = threadIdx.x;
    const int wid = tid >> 5;
    const int lane = tid & 31;
    const int row0 = blockIdx.y * 128;
    const int col0 = blockIdx.x * 128;
    const int NC = K / 64;

    const int wm = wid >> 2;          // 0..1 : warp row (64 rows)
    const int wn = wid & 3;           // 0..3 : warp col (32 cols)

    float acc[4][4][4];               // 64 regs
    #pragma unroll
    for (int i = 0; i < 4; i++)
        #pragma unroll
        for (int j = 0; j < 4; j++)
            #pragma unroll
            for (int r = 0; r < 4; r++) acc[i][j][r] = 0.f;

    const int grp = lane >> 3;
    const int wit = lane & 7;
    const int a_r = wit + (grp & 1) * 8;
    const int a_c = (grp >> 1) * 16;
    const int b_r = wit + (grp >> 1) * 8;
    const int b_c = (grp & 1) * 16;

    // prologue: chunks 0,1 -> stages 0,1
    #pragma unroll
    for (int i = 0; i < 2; i++) {
        uint32_t stb = sb + i * STAGE_BYTES;
        load_tile(stb + A_OFF, A, row0, K, i * 64, tid);
        load_tile(stb + B_OFF, B, col0, K, i * 64, tid);
        CP_COMMIT();
    }

    for (int i = 0; i < NC; i++) {
        if (i + 2 < NC) {
            uint32_t stb = sb + ((i + 2) % 3) * STAGE_BYTES;
            load_tile(stb + A_OFF, A, row0, K, (i + 2) * 64, tid);
            load_tile(stb + B_OFF, B, col0, K, (i + 2) * 64, tid);
            CP_COMMIT();
            CP_WAIT_N(2);
        } else if (i + 1 < NC) {
            CP_WAIT_N(1);
        } else {
            CP_WAIT_N(0);
        }
        __syncthreads();

        const uint32_t sA = sb + (i % 3) * STAGE_BYTES + A_OFF;
        const uint32_t sB = sb + (i % 3) * STAGE_BYTES + B_OFF;

        #pragma unroll
        for (int ks = 0; ks < 4; ks++) {
            const int kb = ks * 32;

            uint32_t ah[4][4];
            #pragma unroll
            for (int mt = 0; mt < 4; mt++) {
                int r = wm * 64 + mt * 16 + a_r;
                ldmat_x4(tile_addr(sA, r, kb + a_c),
                         ah[mt][0], ah[mt][1], ah[mt][2], ah[mt][3]);
            }
            uint32_t bh[4][2];
            #pragma unroll
            for (int np = 0; np < 2; np++) {
                int r = wn * 32 + np * 16 + b_r;
                uint32_t t0, t1, t2, t3;
                ldmat_x4(tile_addr(sB, r, kb + b_c), t0, t1, t2, t3);
                bh[2*np][0] = t0; bh[2*np][1] = t1;
                bh[2*np+1][0] = t2; bh[2*np+1][1] = t3;
            }

            #pragma unroll
            for (int mt = 0; mt < 4; mt++)
                #pragma unroll
                for (int nj = 0; nj < 4; nj++)
                    mma_f16(acc[mt][nj], ah[mt][0], ah[mt][1], ah[mt][2], ah[mt][3],
                            bh[nj][0], bh[nj][1]);
        }
        __syncthreads();
    }

    // epilogue
    #pragma unroll
    for (int mt = 0; mt < 4; mt++) {
        #pragma unroll
        for (int nj = 0; nj < 4; nj++) {
            int m = row0 + wm * 64 + mt * 16 + (lane >> 2);
            int n = col0 + wn * 32 + nj * 8 + (lane & 3) * 2;   // even
            #pragma unroll
            for (int half = 0; half < 2; half++) {
                int mm = m + half * 8;
                float v0 = acc[mt][nj][half * 2 + 0];
                float v1 = acc[mt][nj][half * 2 + 1];
                if (MODE == 1) {
                    out[(size_t)mm * DMODEL + n]     = v0;
                    out[(size_t)mm * DMODEL + n + 1] = v1;
                } else {
                    if (n < DINNER) {
                        *(__half2*)&g_z[(size_t)mm * DINNER + n] =
                            __floats2half2_rn(v0, v1);
                    } else if (n < DINNER + CONVDIM) {
                        *(__half2*)&g_xBC[(size_t)mm * CONVDIM + (n - DINNER)] =
                            __floats2half2_rn(v0, v1);
                    } else if (n < DPROJ) {
                        int h = n - (DINNER + CONVDIM);
                        g_dt[(size_t)mm * NHEADS + h] =
                            softplus_f(v0 + dt_bias[h]);
                        g_dt[(size_t)mm * NHEADS + h + 1] =
                            softplus_f(v1 + dt_bias[h + 1]);
                    }
                }
            }
        }
    }
}

// ============================================================================
// converts
// ============================================================================
__global__ void cvt_half4(const float4* __restrict__ src,
                          __half2* __restrict__ dst, int n4)
{
    int i = blockIdx.x * blockDim.x + threadIdx.x;
    if (i >= n4) return;
    float4 v = src[i];
    dst[2 * i + 0] = __floats2half2_rn(v.x, v.y);
    dst[2 * i + 1] = __floats2half2_rn(v.z, v.w);
}

__global__ void cvt_w1_pad(const float* __restrict__ W)
{
    int i = blockIdx.x * blockDim.x + threadIdx.x;   // over NPAD1*DMODEL
    if (i >= NPAD1 * DMODEL) return;
    int r = i / DMODEL;
    float x = (r < DPROJ) ? W[(size_t)r * DMODEL + (i - r * DMODEL)] : 0.f;
    g_W1h[i] = __float2half(x);
}

// ============================================================================
// Causal depthwise conv + SiLU + split — sliding window, half2 (2 ch/thread).
// ============================================================================
__global__ void conv_silu_kernel(const float* __restrict__ conv_w,
                                 const float* __restrict__ conv_b)
{
    const int ch2 = blockIdx.y * 260 + threadIdx.x;   // 0..1039
    const int ch = ch2 * 2;
    const int bt = blockIdx.x;
    const int b = bt >> 5;
    const int tile = bt & 31;
    const int l0 = tile * 128;
    const int hh = ch >> 8;

    const float4 wa = *(const float4*)&conv_w[ch * 4];
    const float4 wb = *(const float4*)&conv_w[ch * 4 + 4];
    const float cba = conv_b[ch];
    const float cbb = conv_b[ch + 1];

    const __half2* xp = (const __half2*)g_xBC;        // row stride 1040
    const size_t rbase = (size_t)(b * SEQ) * 1040 + ch2;

    float2 xm3 = {0.f, 0.f}, xm2 = {0.f, 0.f}, xm1 = {0.f, 0.f};
    if (l0 > 0) {
        xm3 = __half22float2(xp[rbase + (size_t)(l0 - 3) * 1040]);
        xm2 = __half22float2(xp[rbase + (size_t)(l0 - 2) * 1040]);
        xm1 = __half22float2(xp[rbase + (size_t)(l0 - 1) * 1040]);
    }

    for (int r = 0; r < 128; r += 4) {
        const int l = l0 + r;
        float2 x0 = __half22float2(xp[rbase + (size_t)(l + 0) * 1040]);
        float2 x1 = __half22float2(xp[rbase + (size_t)(l + 1) * 1040]);
        float2 x2 = __half22float2(xp[rbase + (size_t)(l + 2) * 1040]);
        float2 x3 = __half22float2(xp[rbase + (size_t)(l + 3) * 1040]);

        float va[4], vb[4];
        va[0] = silu_f(cba + wa.x * xm3.x + wa.y * xm2.x + wa.z * xm1.x + wa.w * x0.x);
        va[1] = silu_f(cba + wa.x * xm2.x + wa.y * xm1.x + wa.z * x0.x  + wa.w * x1.x);
        va[2] = silu_f(cba + wa.x * xm1.x + wa.y * x0.x  + wa.z * x1.x  + wa.w * x2.x);
        va[3] = silu_f(cba + wa.x * x0.x  + wa.y * x1.x  + wa.z * x2.x  + wa.w * x3.x);
        vb[0] = silu_f(cbb + wb.x * xm3.y + wb.y * xm2.y + wb.z * xm1.y + wb.w * x0.y);
        vb[1] = silu_f(cbb + wb.x * xm2.y + wb.y * xm1.y + wb.z * x0.y  + wb.w * x1.y);
        vb[2] = silu_f(cbb + wb.x * xm1.y + wb.y * x0.y  + wb.z * x1.y  + wb.w * x2.y);
        vb[3] = silu_f(cbb + wb.x * x0.y  + wb.y * x1.y  + wb.z * x2.y  + wb.w * x3.y);

        #pragma unroll
        for (int q = 0; q < 4; q++) {
            const int row = b * SEQ + l + q;
            if (ch < DINNER) {
                float dtv = g_dt[(size_t)row * NHEADS + hh];
                *(__half2*)&g_xh[(size_t)row * DINNER + ch] =
                    __floats2half2_rn(va[q] * dtv, vb[q] * dtv);
            } else if (ch < DINNER + DSTATE) {
                g_Bm[(size_t)row * DSTATE + (ch - DINNER)]     = va[q];
                g_Bm[(size_t)row * DSTATE + (ch - DINNER) + 1] = vb[q];
            } else {
                g_Cm[(size_t)row * DSTATE + (ch - DINNER - DSTATE)]     = va[q];
                g_Cm[(size_t)row * DSTATE + (ch - DINNER - DSTATE) + 1] = vb[q];
            }
        }
        xm3 = x1; xm2 = x2; xm1 = x3;
    }
}

// ============================================================================
// Per-chunk states (fp16 out, fp32 accum)
// ============================================================================
__global__ void chunk_states_kernel(const float* __restrict__ log_A)
{
    const int id = blockIdx.x;
    const int b = id >> 9;
    const int rem = id & 511;
    const int c = rem >> 3;
    const int h = rem & 7;
    const float a = -expf(log_A[h]);

    __shared__ float Bs[CHUNKL][DSTATE];
    const int t = threadIdx.x;
    for (int i = t; i < CHUNKL * DSTATE; i += 256)
        Bs[i >> 4][i & 15] =
            g_Bm[(size_t)(b * SEQ + c * CHUNKL + (i >> 4)) * DSTATE + (i & 15)];
    __syncthreads();

    float acc[DSTATE];
    #pragma unroll
    for (int n = 0; n < DSTATE; n++) acc[n] = 0.f;

    const int p = t;
    for (int s = 0; s < CHUNKL; s++) {
        float xv = __half2float(
            g_xh[(size_t)(b * SEQ + c * CHUNKL + s) * DINNER + h * HEADDIM + p]);
        float w = expf(a * (float)(CHUNKL - 1 - s)) * xv;
        #pragma unroll
        for (int n = 0; n < DSTATE; n++) acc[n] += Bs[s][n] * w;
    }
    size_t base = ((size_t)id * HEADDIM + p) * DSTATE;
    #pragma unroll
    for (int n = 0; n < DSTATE; n += 2)
        *(__half2*)&g_states[base + n] = __floats2half2_rn(acc[n], acc[n + 1]);
}

// ============================================================================
// Inter-chunk scan (fp16 in/out, fp32 recurrence)
// ============================================================================
__global__ void state_scan_kernel(const float* __restrict__ log_A)
{
    const int gid = blockIdx.x * blockDim.x + threadIdx.x;   // over half2 units
    const int b = gid >> 14;
    const int r = gid & 16383;                 // h*2048 + p*8 + n2
    const int h = r >> 11;
    const float a = -expf(log_A[h]);
    const float d = expf(a * (float)CHUNKL);
    float2 P = {0.f, 0.f};
    const __half2* st = (const __half2*)g_states;
    __half2* ps = (__half2*)g_Pst;
    for (int c = 0; c < NCHUNK; c++) {
        size_t off = (size_t)(b * NCHUNK + c) * 16384 + r;
        ps[off] = __floats2half2_rn(P.x, P.y);
        float2 s = __half22float2(st[off]);
        P.x = d * P.x + s.x;
        P.y = d * P.y + s.y;
    }
}

// ============================================================================
// SSD Y kernel — float4 G rows + 4-row tt blocking; fp16 xh/Pst in, Y out
// ============================================================================
__global__ void ssd_y_kernel(const float* __restrict__ log_A,
                             const float* __restrict__ D_skip)
{
    extern __shared__ float sh[];
    float* Bs = sh;                   // 64*16
    float* Cs = sh + 1024;            // 64*16
    float* G  = sh + 2048;            // 64*64
    float* xs = sh + 6144;            // 64*256

    const int id = blockIdx.x;
    const int b = id >> 9;
    const int rem = id & 511;
    const int c = rem >> 3;
    const int h = rem & 7;
    const float a = -expf(log_A[h]);
    const int t = threadIdx.x;
    const int rowbase = b * SEQ + c * CHUNKL;

    for (int i = t; i < CHUNKL * DSTATE; i += 256) {
        size_t gi = (size_t)(rowbase + (i >> 4)) * DSTATE + (i & 15);
        Bs[i] = g_Bm[gi];
        Cs[i] = g_Cm[gi];
    }
    for (int i = t; i < CHUNKL * HEADDIM; i += 256) {
        int s = i >> 8, p = i & 255;
        xs[i] = __half2float(
            g_xh[(size_t)(rowbase + s) * DINNER + h * HEADDIM + p]);
    }
    __syncthreads();

    for (int e = t * 16; e < t * 16 + 16; e++) {
        int tt = e >> 6, ss = e & 63;
        float val = 0.f;
        if (ss <= tt) {
            float dot = 0.f;
            #pragma unroll
            for (int n = 0; n < DSTATE; n++) dot += Cs[tt * 16 + n] * Bs[ss * 16 + n];
            val = expf(a * (float)(tt - ss)) * dot;
        }
        G[e] = val;
    }
    __syncthreads();

    const int p = t;
    float Preg[DSTATE];
    size_t pbase = ((size_t)id * HEADDIM + p) * DSTATE;
    #pragma unroll
    for (int n = 0; n < DSTATE; n += 2) {
        float2 pv = __half22float2(*(const __half2*)&g_Pst[pbase + n]);
        Preg[n] = pv.x; Preg[n + 1] = pv.y;
    }
    const float dsk = D_skip[h];

    for (int tt0 = 0; tt0 < CHUNKL; tt0 += 4) {
        float aq[4] = {0.f, 0.f, 0.f, 0.f};
        const int smax = tt0 + 4;
        for (int ss = 0; ss < smax; ss += 4) {
            float xv0 = xs[(ss + 0) * 256 + p];
            float xv1 = xs[(ss + 1) * 256 + p];
            float xv2 = xs[(ss + 2) * 256 + p];
            float xv3 = xs[(ss + 3) * 256 + p];
            #pragma unroll
            for (int q = 0; q < 4; q++) {
                float4 g4 = *(const float4*)&G[(tt0 + q) * 64 + ss];
                aq[q] += g4.x * xv0 + g4.y * xv1 + g4.z * xv2 + g4.w * xv3;
            }
        }
        #pragma unroll
        for (int q = 0; q < 4; q++) {
            const int tt = tt0 + q;
            float offv = 0.f;
            const float4* c4 = (const float4*)&Cs[tt * 16];
            #pragma unroll
            for (int n4 = 0; n4 < 4; n4++) {
                float4 cv = c4[n4];
                offv += cv.x * Preg[n4 * 4 + 0] + cv.y * Preg[n4 * 4 + 1] +
                        cv.z * Preg[n4 * 4 + 2] + cv.w * Preg[n4 * 4 + 3];
            }
            float y = aq[q] + expf(a * (float)(tt + 1)) * offv +
                      dsk * xs[tt * 256 + p];
            g_Y[(size_t)(rowbase + tt) * DINNER + h * HEADDIM + p] =
                __float2half(y);
        }
    }
}

// ============================================================================
// Gate + RMS norm; fp16 in (Y, z), fp16 out (Yh)
// ============================================================================
__global__ void rms_gate_kernel(const float* __restrict__ norm_w)
{
    const int row = blockIdx.x;
    const int t = threadIdx.x;
    float v[8];
    float ss = 0.f;
    #pragma unroll
    for (int k = 0; k < 8; k++) {
        int ch = k * 256 + t;
        float Yv = __half2float(g_Y[(size_t)row * DINNER + ch]);
        float zv = __half2float(g_z[(size_t)row * DINNER + ch]);
        float val = Yv * silu_f(zv);
        v[k] = val;
        ss += val * val;
    }
    __shared__ float red[256];
    red[t] = ss;
    __syncthreads();
    for (int st = 128; st > 0; st >>= 1) {
        if (t < st) red[t] += red[t + st];
        __syncthreads();
    }
    float inv = rsqrtf(red[0] / (float)DINNER + 1e-5f);
    #pragma unroll
    for (int k = 0; k < 8; k++) {
        int ch = k * 256 + t;
        g_Yh[(size_t)row * DINNER + ch] = __float2half(v[k] * inv * norm_w[ch]);
    }
}

// ============================================================================
// Launch
// ============================================================================
extern "C" void kernel_launch(void* const* d_in, const int* in_sizes, int n_in,
                              void* d_out, int out_size)
{
    const float* input   = (const float*)d_in[0];
    const float* W_in    = (const float*)d_in[1];
    const float* conv_w  = (const float*)d_in[2];
    const float* conv_b  = (const float*)d_in[3];
    const float* dt_bias = (const float*)d_in[4];
    const float* log_A   = (const float*)d_in[5];
    const float* D_skip  = (const float*)d_in[6];
    const float* norm_w  = (const float*)d_in[7];
    const float* W_out   = (const float*)d_in[8];
    float* out = (float*)d_out;

    (void)in_sizes; (void)n_in; (void)out_size;

    const int GSMEM = 3 * STAGE_BYTES;               // 98304 B per CTA
    const int SMEM_Y = (1024 + 1024 + 4096 + 16384) * 4;
    cudaFuncSetAttribute(mma_gemm<0>, cudaFuncAttributeMaxDynamicSharedMemorySize, GSMEM);
    cudaFuncSetAttribute(mma_gemm<1>, cudaFuncAttributeMaxDynamicSharedMemorySize, GSMEM);
    cudaFuncSetAttribute(ssd_y_kernel, cudaFuncAttributeMaxDynamicSharedMemorySize, SMEM_Y);

    __half *Xh, *W2h, *Yh, *W1h;
    cudaGetSymbolAddress((void**)&Xh,  g_Xh);
    cudaGetSymbolAddress((void**)&W2h, g_W2h);
    cudaGetSymbolAddress((void**)&Yh,  g_Yh);
    cudaGetSymbolAddress((void**)&W1h, g_W1h);

    // converts (vectorized)
    {
        int n4 = NROWS * DMODEL / 4;
        cvt_half4<<<(n4 + 255) / 256, 256>>>((const float4*)input,
                                             (__half2*)Xh, n4);
    }
    cvt_w1_pad<<<(NPAD1 * DMODEL + 255) / 256, 256>>>(W_in);
    {
        int n4 = DMODEL * DINNER / 4;
        cvt_half4<<<(n4 + 255) / 256, 256>>>((const float4*)W_out,
                                             (__half2*)W2h, n4);
    }

    // 1) in-projection
    mma_gemm<0><<<dim3(NPAD1 / 128, NROWS / 128), 256, GSMEM>>>(
        Xh, W1h, DMODEL, nullptr, dt_bias);

    // 2) conv + silu + split (half2 sliding window)
    conv_silu_kernel<<<dim3(BATCH * 32, 4), 260>>>(conv_w, conv_b);

    // 3) per-chunk states
    chunk_states_kernel<<<BATCH * NCHUNK * NHEADS, 256>>>(log_A);

    // 4) inter-chunk scan (half2 lanes)
    state_scan_kernel<<<(BATCH * NHEADS * HEADDIM * DSTATE / 2) / 256, 256>>>(log_A);

    // 5) Y
    ssd_y_kernel<<<BATCH * NCHUNK * NHEADS, 256, SMEM_Y>>>(log_A, D_skip);

    // 6) gate + RMS norm
    rms_gate_kernel<<<NROWS, 256>>>(norm_w);

    // 7) out-projection
    mma_gemm<1><<<dim3(DMODEL / 128, NROWS / 128), 256, GSMEM>>>(
        Yh, W2h, DINNER, out, nullptr);
}